// round 7
// baseline (speedup 1.0000x reference)
#include <cuda_runtime.h>
#include <cuda_fp16.h>
#include <math.h>
#include <stdint.h>

// Problem dimensions (fixed)
#define SEQ   2048
#define DIN   11008
#define DOUT  4096
#define KR    4096

// ---------------------------------------------------------------------------
// Scratch (__device__ globals; no cudaMalloc allowed)
// ---------------------------------------------------------------------------
__device__ float  g_W [(size_t)DOUT * DIN];   // W' fp32 [o][i]
__device__ __half g_Q [(size_t)DOUT * DIN];   // quantized ints as fp16 [o][i]
__device__ __half g_A0[(size_t)DOUT * KR];    // (R^T * 64) hi  [o][k]
__device__ __half g_A1[(size_t)DOUT * KR];    // lo
__device__ __half g_B0[(size_t)DIN  * KR];    // ((w*S)^T * 64) hi [i][k]
__device__ __half g_B1[(size_t)DIN  * KR];    // lo
__device__ __half g_X0[(size_t)SEQ  * DIN];   // x hi [s][i]
__device__ __half g_X1[(size_t)SEQ  * DIN];   // x lo
__device__ float  g_wscale[DOUT];
__device__ float  g_bias  [DOUT];

// ---------------------------------------------------------------------------
// PTX helpers (sm_100 base target: cp.async + ldmatrix + mma.sync)
// ---------------------------------------------------------------------------
__device__ __forceinline__ uint32_t smem_u32(const void* p) {
    return (uint32_t)__cvta_generic_to_shared(p);
}
__device__ __forceinline__ void cp16(uint32_t s, const void* g) {
    asm volatile("cp.async.cg.shared.global [%0], [%1], 16;\n" :: "r"(s), "l"(g));
}
__device__ __forceinline__ void cp_commit() {
    asm volatile("cp.async.commit_group;" ::: "memory");
}
template<int N>
__device__ __forceinline__ void cp_wait() {
    asm volatile("cp.async.wait_group %0;" :: "n"(N) : "memory");
}
__device__ __forceinline__ void ldm4(uint32_t* r, uint32_t addr) {
    asm volatile("ldmatrix.sync.aligned.m8n8.x4.shared.b16 {%0,%1,%2,%3}, [%4];"
        : "=r"(r[0]), "=r"(r[1]), "=r"(r[2]), "=r"(r[3]) : "r"(addr));
}
__device__ __forceinline__ void mma16816(float* d, const uint32_t* a, uint32_t b0, uint32_t b1) {
    asm volatile("mma.sync.aligned.m16n8k16.row.col.f32.f16.f16.f32 "
        "{%0,%1,%2,%3}, {%4,%5,%6,%7}, {%8,%9}, {%0,%1,%2,%3};"
        : "+f"(d[0]), "+f"(d[1]), "+f"(d[2]), "+f"(d[3])
        : "r"(a[0]), "r"(a[1]), "r"(a[2]), "r"(a[3]), "r"(b0), "r"(b1));
}

// ---------------------------------------------------------------------------
// Multistage fp16 GEMM: C[M][N] = alpha * sum_t A_t[M][K] @ B_t[N][K]^T (+epi)
// CTA tile 128x256x32, 256 threads = 8 warps (2 M x 4 N), warp tile 64x64.
// 4-stage cp.async pipeline; smem swizzle: chunk c at row r -> c ^ ((r>>1)&3).
// ---------------------------------------------------------------------------
struct TermsH { const __half* A[3]; const __half* B[3]; };

#define STAGES   4
#define A_STAGE  8192
#define B_STAGE  16384
#define SM_STAGE (A_STAGE + B_STAGE)
#define SMEM_DYN (STAGES * SM_STAGE + 1024)

__global__ __launch_bounds__(256)
void gemm_mma(TermsH t, int nT, int K, float* __restrict__ C, int ldc, float alpha,
              const float* __restrict__ cs, const float* __restrict__ cb)
{
    extern __shared__ char raw[];
    const uint32_t base = (smem_u32(raw) + 1023u) & ~1023u;

    const int tid  = threadIdx.x;
    const int lane = tid & 31, wid = tid >> 5;
    const int wr   = wid & 1, wc = wid >> 1;          // 2 x 4 warp grid
    const int m0   = blockIdx.x * 128, n0 = blockIdx.y * 256;

    // loaders: A = 512 chunks (128 rows x 4 x 16B) -> 2/thread;
    //          B = 1024 chunks (256 rows x 4 x 16B) -> 4/thread
    uint32_t aso[2], ago[2], bso[4], bgo[4];
    #pragma unroll
    for (int j = 0; j < 2; j++) {
        int ch = tid + j * 256, r = ch >> 2, c = ch & 3;
        aso[j] = (uint32_t)(r * 64 + ((c ^ ((r >> 1) & 3)) << 4));
        ago[j] = (uint32_t)(r * K + c * 8);
    }
    #pragma unroll
    for (int j = 0; j < 4; j++) {
        int ch = tid + j * 256, r = ch >> 2, c = ch & 3;
        bso[j] = (uint32_t)(r * 64 + ((c ^ ((r >> 1) & 3)) << 4));
        bgo[j] = (uint32_t)(r * K + c * 8);
    }

    // ldmatrix per-lane byte offsets
    uint32_t aoff[2][4], boff[2][4];
    #pragma unroll
    for (int ks = 0; ks < 2; ks++) {
        #pragma unroll
        for (int mf = 0; mf < 4; mf++) {
            int r = wr * 64 + mf * 16 + (lane & 15);
            int c = ks * 2 + (lane >> 4);
            aoff[ks][mf] = (uint32_t)(r * 64 + ((c ^ ((r >> 1) & 3)) << 4));
        }
        #pragma unroll
        for (int nf = 0; nf < 4; nf++) {
            int r = wc * 64 + nf * 16 + (lane & 7) + ((lane >> 4) << 3);
            int c = ks * 2 + ((lane >> 3) & 1);
            boff[ks][nf] = (uint32_t)(r * 64 + ((c ^ ((r >> 1) & 3)) << 4));
        }
    }

    const int kpt   = K >> 5;
    const int total = nT * kpt;
    int lt = 0, lk = 0;
    auto issue = [&](int stage) {
        const __half* ga = t.A[lt] + (size_t)m0 * K + lk * 32;
        const __half* gb = t.B[lt] + (size_t)n0 * K + lk * 32;
        const uint32_t sa = base + stage * SM_STAGE;
        const uint32_t sb = sa + A_STAGE;
        #pragma unroll
        for (int j = 0; j < 2; j++) cp16(sa + aso[j], ga + ago[j]);
        #pragma unroll
        for (int j = 0; j < 4; j++) cp16(sb + bso[j], gb + bgo[j]);
        if (++lk == kpt) { lk = 0; ++lt; }
    };

    float acc[4][8][4];
    #pragma unroll
    for (int i = 0; i < 4; i++)
        #pragma unroll
        for (int j = 0; j < 8; j++)
            #pragma unroll
            for (int k = 0; k < 4; k++) acc[i][j][k] = 0.0f;

    #pragma unroll
    for (int s = 0; s < STAGES - 1; s++) {
        if (s < total) issue(s);
        cp_commit();
    }

    for (int i = 0; i < total; i++) {
        cp_wait<STAGES - 2>();
        __syncthreads();

        const int ns = i + STAGES - 1;
        if (ns < total) issue(ns & 3);
        cp_commit();

        const uint32_t sa = base + (i & 3) * SM_STAGE;
        const uint32_t sb = sa + A_STAGE;

        #pragma unroll
        for (int ks = 0; ks < 2; ks++) {
            uint32_t af[4][4], bf[4][4];
            #pragma unroll
            for (int mf = 0; mf < 4; mf++) ldm4(af[mf], sa + aoff[ks][mf]);
            #pragma unroll
            for (int nf = 0; nf < 4; nf++) ldm4(bf[nf], sb + boff[ks][nf]);
            #pragma unroll
            for (int mf = 0; mf < 4; mf++)
                #pragma unroll
                for (int nf = 0; nf < 4; nf++) {
                    mma16816(acc[mf][nf * 2],     af[mf], bf[nf][0], bf[nf][1]);
                    mma16816(acc[mf][nf * 2 + 1], af[mf], bf[nf][2], bf[nf][3]);
                }
        }
    }

    // epilogue: d0,d1 -> (row, col..col+1); d2,d3 -> (row+8, ...)
    const int ln4 = lane >> 2, lq = lane & 3;
    #pragma unroll
    for (int mf = 0; mf < 4; mf++) {
        #pragma unroll
        for (int h = 0; h < 2; h++) {
            const int row = m0 + wr * 64 + mf * 16 + ln4 + h * 8;
            float* crow = C + (size_t)row * ldc;
            #pragma unroll
            for (int nf = 0; nf < 8; nf++) {
                const int col = n0 + wc * 64 + nf * 8 + lq * 2;
                float v0 = acc[mf][nf][h * 2]     * alpha;
                float v1 = acc[mf][nf][h * 2 + 1] * alpha;
                if (cs) {
                    v0 = v0 * __ldg(&cs[col])     + __ldg(&cb[col]);
                    v1 = v1 * __ldg(&cs[col + 1]) + __ldg(&cb[col + 1]);
                }
                *(float2*)&crow[col] = make_float2(v0, v1);
            }
        }
    }
}

// ---------------------------------------------------------------------------
// Prep: transpose + pre-scale + 2-way fp16 split.
// ---------------------------------------------------------------------------
__global__ void tsplit2h(const float* __restrict__ src, int rows, int cols,
                         const float* __restrict__ colScale, float mul,
                         __half* __restrict__ o0, __half* __restrict__ o1)
{
    __shared__ float tsh[32][33];
    const int c0 = blockIdx.x * 32, r0 = blockIdx.y * 32;
    #pragma unroll
    for (int rr = threadIdx.y; rr < 32; rr += 8)
        tsh[rr][threadIdx.x] = src[(size_t)(r0 + rr) * cols + c0 + threadIdx.x];
    __syncthreads();
    #pragma unroll
    for (int cc = threadIdx.y; cc < 32; cc += 8) {
        const int c = c0 + cc;
        float v = tsh[threadIdx.x][cc] * mul;
        if (colScale) v *= colScale[c];
        __half hi = __float2half_rn(v);
        __half lo = __float2half_rn(v - __half2float(hi));
        const size_t off = (size_t)c * rows + r0 + threadIdx.x;
        o0[off] = hi; o1[off] = lo;
    }
}

// ---------------------------------------------------------------------------
// x -> 2-way fp16 split (elementwise, vectorized)
// ---------------------------------------------------------------------------
__device__ __forceinline__ uint32_t packh(__half a, __half b) {
    uint16_t ua = *(uint16_t*)&a, ub = *(uint16_t*)&b;
    return (uint32_t)ua | ((uint32_t)ub << 16);
}
__global__ void split2h(const float* __restrict__ x,
                        __half* __restrict__ o0, __half* __restrict__ o1)
{
    const size_t i = (size_t)blockIdx.x * blockDim.x + threadIdx.x;
    float4 v = ((const float4*)x)[i];
    __half hx = __float2half_rn(v.x), hy = __float2half_rn(v.y);
    __half hz = __float2half_rn(v.z), hw = __float2half_rn(v.w);
    __half lx = __float2half_rn(v.x - __half2float(hx));
    __half ly = __float2half_rn(v.y - __half2float(hy));
    __half lz = __float2half_rn(v.z - __half2float(hz));
    __half lw = __float2half_rn(v.w - __half2float(hw));
    ((uint2*)o0)[i] = make_uint2(packh(hx, hy), packh(hz, hw));
    ((uint2*)o1)[i] = make_uint2(packh(lx, ly), packh(lz, lw));
}

// ---------------------------------------------------------------------------
// Rotated bias: b'[o] = sum_k R[k][o] * bias[k]
// ---------------------------------------------------------------------------
__global__ void rot_bias_kernel(const float* __restrict__ R,
                                const float* __restrict__ bias,
                                float* __restrict__ out)
{
    const int o = blockIdx.x * blockDim.x + threadIdx.x;
    if (o >= DOUT) return;
    float acc = 0.0f;
    for (int k = 0; k < KR; k++)
        acc = fmaf(R[(size_t)k * DOUT + o], bias[k], acc);
    out[o] = acc;
}

// ---------------------------------------------------------------------------
// Per-row max(|W'|) -> quant scale
// ---------------------------------------------------------------------------
__device__ __forceinline__ float block_reduce_max(float v) {
    __shared__ float sh[32];
    int lane = threadIdx.x & 31;
    int wid  = threadIdx.x >> 5;
    #pragma unroll
    for (int o = 16; o; o >>= 1) v = fmaxf(v, __shfl_xor_sync(0xffffffffu, v, o));
    if (lane == 0) sh[wid] = v;
    __syncthreads();
    int nw = blockDim.x >> 5;
    v = (threadIdx.x < (unsigned)nw) ? sh[threadIdx.x] : 0.0f;
    if (wid == 0) {
        #pragma unroll
        for (int o = 16; o; o >>= 1) v = fmaxf(v, __shfl_xor_sync(0xffffffffu, v, o));
    }
    if (threadIdx.x == 0) sh[0] = v;
    __syncthreads();
    return sh[0];
}
__global__ void wrowmax_kernel(const float* __restrict__ W, float* __restrict__ scale)
{
    const int row = blockIdx.x;
    const float* p = W + (size_t)row * DIN;
    float m = 0.0f;
    for (int i = threadIdx.x * 4; i < DIN; i += blockDim.x * 4) {
        float4 v = *(const float4*)&p[i];
        m = fmaxf(m, fmaxf(fmaxf(fabsf(v.x), fabsf(v.y)), fmaxf(fabsf(v.z), fabsf(v.w))));
    }
    m = block_reduce_max(m);
    if (threadIdx.x == 0)
        scale[row] = fmaxf(__fdiv_rn(m, 127.0f), 1e-8f);
}

// ---------------------------------------------------------------------------
// 8-bit fake-quant to fp16 integers (exact): q = clamp(rint(W/s_o))
// ---------------------------------------------------------------------------
__global__ void quant_h_kernel(const float* __restrict__ W,
                               const float* __restrict__ scale,
                               __half* __restrict__ q)
{
    const size_t idx4 = (size_t)blockIdx.x * blockDim.x + threadIdx.x;
    const int row = (int)(idx4 / (DIN / 4));
    const float s = scale[row];
    float4 v = ((const float4*)W)[idx4];
    float qx = fminf(fmaxf(rintf(__fdiv_rn(v.x, s)), -128.0f), 127.0f);
    float qy = fminf(fmaxf(rintf(__fdiv_rn(v.y, s)), -128.0f), 127.0f);
    float qz = fminf(fmaxf(rintf(__fdiv_rn(v.z, s)), -128.0f), 127.0f);
    float qw = fminf(fmaxf(rintf(__fdiv_rn(v.w, s)), -128.0f), 127.0f);
    ((uint2*)q)[idx4] = make_uint2(
        packh(__float2half_rn(qx), __float2half_rn(qy)),
        packh(__float2half_rn(qz), __float2half_rn(qw)));
}

// ---------------------------------------------------------------------------
// 16-bit per-token fake-quant, in place
// ---------------------------------------------------------------------------
__global__ void out_quant_kernel(float* __restrict__ out)
{
    const int s = blockIdx.x;
    float* p = out + (size_t)s * DOUT;
    float m = 0.0f;
    for (int i = threadIdx.x * 4; i < DOUT; i += blockDim.x * 4) {
        float4 v = *(const float4*)&p[i];
        m = fmaxf(m, fmaxf(fmaxf(fabsf(v.x), fabsf(v.y)), fmaxf(fabsf(v.z), fabsf(v.w))));
    }
    m = block_reduce_max(m);
    const float sc = fmaxf(__fdiv_rn(m, 32767.0f), 1e-8f);
    for (int i = threadIdx.x * 4; i < DOUT; i += blockDim.x * 4) {
        float4 v = *(const float4*)&p[i];
        v.x = fminf(fmaxf(rintf(__fdiv_rn(v.x, sc)), -32768.0f), 32767.0f) * sc;
        v.y = fminf(fmaxf(rintf(__fdiv_rn(v.y, sc)), -32768.0f), 32767.0f) * sc;
        v.z = fminf(fmaxf(rintf(__fdiv_rn(v.z, sc)), -32768.0f), 32767.0f) * sc;
        v.w = fminf(fmaxf(rintf(__fdiv_rn(v.w, sc)), -32768.0f), 32767.0f) * sc;
        *(float4*)&p[i] = v;
    }
}

// ---------------------------------------------------------------------------
// Launch
// ---------------------------------------------------------------------------
extern "C" void kernel_launch(void* const* d_in, const int* in_sizes, int n_in,
                              void* d_out, int out_size)
{
    const float* d_x = (const float*)d_in[0];
    const float* d_w = (const float*)d_in[1];
    const float* d_b = (const float*)d_in[2];
    const float* d_S = (const float*)d_in[3];
    const float* d_R = (const float*)d_in[4];
    float*       d_o = (float*)d_out;

    float *gW, *gws, *gbias;
    __half *gQ, *gA0, *gA1, *gB0, *gB1, *gX0, *gX1;
    cudaGetSymbolAddress((void**)&gW,   g_W);
    cudaGetSymbolAddress((void**)&gQ,   g_Q);
    cudaGetSymbolAddress((void**)&gA0,  g_A0);
    cudaGetSymbolAddress((void**)&gA1,  g_A1);
    cudaGetSymbolAddress((void**)&gB0,  g_B0);
    cudaGetSymbolAddress((void**)&gB1,  g_B1);
    cudaGetSymbolAddress((void**)&gX0,  g_X0);
    cudaGetSymbolAddress((void**)&gX1,  g_X1);
    cudaGetSymbolAddress((void**)&gws,  g_wscale);
    cudaGetSymbolAddress((void**)&gbias, g_bias);

    cudaFuncSetAttribute(gemm_mma, cudaFuncAttributeMaxDynamicSharedMemorySize, SMEM_DYN);

    // 1) rotated bias
    rot_bias_kernel<<<DOUT / 256, 256>>>(d_R, d_b, gbias);

    // 2) prep splits (pre-scaled by 2^6 each so lo stays in fp16 normal range)
    tsplit2h<<<dim3(DOUT / 32, KR / 32), dim3(32, 8)>>>(d_R, KR, DOUT, nullptr, 64.0f, gA0, gA1);
    tsplit2h<<<dim3(DIN / 32, KR / 32),  dim3(32, 8)>>>(d_w, KR, DIN,  d_S,    64.0f, gB0, gB1);
    split2h<<<(int)((size_t)SEQ * DIN / 4 / 256), 256>>>(d_x, gX0, gX1);

    // 3) GEMM1: W' = R^T (weight*S), 3-term fp16 split, alpha = 2^-12 un-scale
    {
        TermsH t;
        t.A[0] = gA0; t.B[0] = gB0;
        t.A[1] = gA0; t.B[1] = gB1;
        t.A[2] = gA1; t.B[2] = gB0;
        dim3 grid(DOUT / 128, DIN / 256);
        gemm_mma<<<grid, 256, SMEM_DYN>>>(t, 3, KR, gW, DIN, 1.0f / 4096.0f, nullptr, nullptr);
    }

    // 4) weight quant scale + quantize to fp16 ints
    wrowmax_kernel<<<DOUT, 256>>>(gW, gws);
    quant_h_kernel<<<(int)((size_t)DOUT * DIN / 4 / 256), 256>>>(gW, gws, gQ);

    // 5) GEMM2: out = (x @ q^T) * s_o + b'_o, 2-term x split (q exact in fp16)
    {
        TermsH t;
        t.A[0] = gX0; t.B[0] = gQ;
        t.A[1] = gX1; t.B[1] = gQ;
        t.A[2] = nullptr; t.B[2] = nullptr;
        dim3 grid(SEQ / 128, DOUT / 256);
        gemm_mma<<<grid, 256, SMEM_DYN>>>(t, 2, DIN, d_o, DOUT, 1.0f, gws, gbias);
    }

    // 6) 16-bit per-token fake-quant in place
    out_quant_kernel<<<SEQ, 256>>>(d_o);
}

// round 9
// speedup vs baseline: 1.0161x; 1.0161x over previous
#include <cuda_runtime.h>
#include <cuda_fp16.h>
#include <math.h>
#include <stdint.h>

// Problem dimensions (fixed)
#define SEQ   2048
#define DIN   11008
#define DOUT  4096
#define KR    4096

// ---------------------------------------------------------------------------
// Scratch (__device__ globals; no cudaMalloc allowed)
// ---------------------------------------------------------------------------
__device__ float  g_W [(size_t)DOUT * DIN];   // W' fp32 [o][i]
__device__ __half g_Q [(size_t)DOUT * DIN];   // quantized ints as fp16 [o][i]
__device__ __half g_A0[(size_t)DOUT * KR];    // (R^T * 64) hi  [o][k]
__device__ __half g_A1[(size_t)DOUT * KR];    // lo
__device__ __half g_B0[(size_t)DIN  * KR];    // ((w*S)^T * 64) hi [i][k]
__device__ __half g_B1[(size_t)DIN  * KR];    // lo
__device__ __half g_X0[(size_t)SEQ  * DIN];   // x hi [s][i]
__device__ __half g_X1[(size_t)SEQ  * DIN];   // x lo
__device__ float  g_wscale[DOUT];
__device__ float  g_bias  [DOUT];

// ---------------------------------------------------------------------------
// PTX helpers
// ---------------------------------------------------------------------------
__device__ __forceinline__ uint32_t smem_u32(const void* p) {
    return (uint32_t)__cvta_generic_to_shared(p);
}
__device__ __forceinline__ void cp16(uint32_t s, const void* g) {
    asm volatile("cp.async.cg.shared.global [%0], [%1], 16;\n" :: "r"(s), "l"(g));
}
__device__ __forceinline__ void cp_commit() {
    asm volatile("cp.async.commit_group;" ::: "memory");
}
template<int N>
__device__ __forceinline__ void cp_wait() {
    asm volatile("cp.async.wait_group %0;" :: "n"(N) : "memory");
}
__device__ __forceinline__ void ldm4(uint32_t* r, uint32_t addr) {
    asm volatile("ldmatrix.sync.aligned.m8n8.x4.shared.b16 {%0,%1,%2,%3}, [%4];"
        : "=r"(r[0]), "=r"(r[1]), "=r"(r[2]), "=r"(r[3]) : "r"(addr));
}
__device__ __forceinline__ void mma16816(float* d, const uint32_t* a, uint32_t b0, uint32_t b1) {
    asm volatile("mma.sync.aligned.m16n8k16.row.col.f32.f16.f16.f32 "
        "{%0,%1,%2,%3}, {%4,%5,%6,%7}, {%8,%9}, {%0,%1,%2,%3};"
        : "+f"(d[0]), "+f"(d[1]), "+f"(d[2]), "+f"(d[3])
        : "r"(a[0]), "r"(a[1]), "r"(a[2]), "r"(a[3]), "r"(b0), "r"(b1));
}

// ---------------------------------------------------------------------------
// Multistage fp16 GEMM: C[M][N] = alpha * sum_t A_t[M][K] @ B_t[N][K]^T (+epi)
// CTA tile 128x256x32, 512 threads = 16 warps (2 M x 8 N), warp tile 64x32
// (identical per-warp layout to the proven 4618us config -> acc stays 64 regs).
// 4-stage cp.async; smem swizzle: chunk c at row r -> c ^ ((r>>1)&3).
// Raises smem-fill arithmetic intensity 64 -> 85 FLOP/B (L2-cap relief).
// ---------------------------------------------------------------------------
struct TermsH { const __half* A[3]; const __half* B[3]; };

#define STAGES   4
#define A_STAGE  8192
#define B_STAGE  16384
#define SM_STAGE (A_STAGE + B_STAGE)
#define SMEM_DYN (STAGES * SM_STAGE + 1024)

__global__ __launch_bounds__(512)
void gemm_mma(TermsH t, int nT, int K, float* __restrict__ C, int ldc, float alpha,
              const float* __restrict__ cs, const float* __restrict__ cb)
{
    extern __shared__ char raw[];
    const uint32_t base = (smem_u32(raw) + 1023u) & ~1023u;

    const int tid  = threadIdx.x;
    const int lane = tid & 31, wid = tid >> 5;
    const int wr   = wid & 1, wc = wid >> 1;          // 2 x 8 warp grid
    const int m0   = blockIdx.x * 128, n0 = blockIdx.y * 256;

    // loaders: A = 512 chunks (128 rows x 4 x 16B) -> 1/thread;
    //          B = 1024 chunks (256 rows x 4 x 16B) -> 2/thread
    uint32_t aso, ago, bso[2], bgo[2];
    {
        int r = tid >> 2, c = tid & 3;
        aso = (uint32_t)(r * 64 + ((c ^ ((r >> 1) & 3)) << 4));
        ago = (uint32_t)(r * K + c * 8);
    }
    #pragma unroll
    for (int j = 0; j < 2; j++) {
        int ch = tid + j * 512, r = ch >> 2, c = ch & 3;
        bso[j] = (uint32_t)(r * 64 + ((c ^ ((r >> 1) & 3)) << 4));
        bgo[j] = (uint32_t)(r * K + c * 8);
    }

    // ldmatrix per-lane byte offsets (warp tile 64 M x 32 N)
    uint32_t aoff[2][4], boff[2][2];
    #pragma unroll
    for (int ks = 0; ks < 2; ks++) {
        #pragma unroll
        for (int mf = 0; mf < 4; mf++) {
            int r = wr * 64 + mf * 16 + (lane & 15);
            int c = ks * 2 + (lane >> 4);
            aoff[ks][mf] = (uint32_t)(r * 64 + ((c ^ ((r >> 1) & 3)) << 4));
        }
        #pragma unroll
        for (int nf = 0; nf < 2; nf++) {
            int r = wc * 32 + nf * 16 + (lane & 7) + ((lane >> 4) << 3);
            int c = ks * 2 + ((lane >> 3) & 1);
            boff[ks][nf] = (uint32_t)(r * 64 + ((c ^ ((r >> 1) & 3)) << 4));
        }
    }

    const int kpt   = K >> 5;
    const int total = nT * kpt;
    int lt = 0, lk = 0;
    auto issue = [&](int stage) {
        const __half* ga = t.A[lt] + (size_t)m0 * K + lk * 32;
        const __half* gb = t.B[lt] + (size_t)n0 * K + lk * 32;
        const uint32_t sa = base + stage * SM_STAGE;
        const uint32_t sb = sa + A_STAGE;
        cp16(sa + aso, ga + ago);
        #pragma unroll
        for (int j = 0; j < 2; j++) cp16(sb + bso[j], gb + bgo[j]);
        if (++lk == kpt) { lk = 0; ++lt; }
    };

    float acc[4][4][4];
    #pragma unroll
    for (int i = 0; i < 4; i++)
        #pragma unroll
        for (int j = 0; j < 4; j++)
            #pragma unroll
            for (int k = 0; k < 4; k++) acc[i][j][k] = 0.0f;

    #pragma unroll
    for (int s = 0; s < STAGES - 1; s++) {
        if (s < total) issue(s);
        cp_commit();
    }

    for (int i = 0; i < total; i++) {
        cp_wait<STAGES - 2>();
        __syncthreads();

        const int ns = i + STAGES - 1;
        if (ns < total) issue(ns & 3);
        cp_commit();

        const uint32_t sa = base + (i & 3) * SM_STAGE;
        const uint32_t sb = sa + A_STAGE;

        #pragma unroll
        for (int ks = 0; ks < 2; ks++) {
            uint32_t af[4][4], bf[2][4];
            #pragma unroll
            for (int mf = 0; mf < 4; mf++) ldm4(af[mf], sa + aoff[ks][mf]);
            #pragma unroll
            for (int np = 0; np < 2; np++) ldm4(bf[np], sb + boff[ks][np]);
            #pragma unroll
            for (int mf = 0; mf < 4; mf++)
                #pragma unroll
                for (int np = 0; np < 2; np++) {
                    mma16816(acc[mf][np * 2],     af[mf], bf[np][0], bf[np][1]);
                    mma16816(acc[mf][np * 2 + 1], af[mf], bf[np][2], bf[np][3]);
                }
        }
    }

    // epilogue: d0,d1 -> (row, col..col+1); d2,d3 -> (row+8, ...)
    const int ln4 = lane >> 2, lq = lane & 3;
    #pragma unroll
    for (int mf = 0; mf < 4; mf++) {
        #pragma unroll
        for (int h = 0; h < 2; h++) {
            const int row = m0 + wr * 64 + mf * 16 + ln4 + h * 8;
            float* crow = C + (size_t)row * ldc;
            #pragma unroll
            for (int nf = 0; nf < 4; nf++) {
                const int col = n0 + wc * 32 + nf * 8 + lq * 2;
                float v0 = acc[mf][nf][h * 2]     * alpha;
                float v1 = acc[mf][nf][h * 2 + 1] * alpha;
                if (cs) {
                    v0 = v0 * __ldg(&cs[col])     + __ldg(&cb[col]);
                    v1 = v1 * __ldg(&cs[col + 1]) + __ldg(&cb[col + 1]);
                }
                *(float2*)&crow[col] = make_float2(v0, v1);
            }
        }
    }
}

// ---------------------------------------------------------------------------
// Prep: transpose + pre-scale + 2-way fp16 split.
// ---------------------------------------------------------------------------
__global__ void tsplit2h(const float* __restrict__ src, int rows, int cols,
                         const float* __restrict__ colScale, float mul,
                         __half* __restrict__ o0, __half* __restrict__ o1)
{
    __shared__ float tsh[32][33];
    const int c0 = blockIdx.x * 32, r0 = blockIdx.y * 32;
    #pragma unroll
    for (int rr = threadIdx.y; rr < 32; rr += 8)
        tsh[rr][threadIdx.x] = src[(size_t)(r0 + rr) * cols + c0 + threadIdx.x];
    __syncthreads();
    #pragma unroll
    for (int cc = threadIdx.y; cc < 32; cc += 8) {
        const int c = c0 + cc;
        float v = tsh[threadIdx.x][cc] * mul;
        if (colScale) v *= colScale[c];
        __half hi = __float2half_rn(v);
        __half lo = __float2half_rn(v - __half2float(hi));
        const size_t off = (size_t)c * rows + r0 + threadIdx.x;
        o0[off] = hi; o1[off] = lo;
    }
}

// ---------------------------------------------------------------------------
// x -> 2-way fp16 split (elementwise, vectorized)
// ---------------------------------------------------------------------------
__device__ __forceinline__ uint32_t packh(__half a, __half b) {
    uint16_t ua = *(uint16_t*)&a, ub = *(uint16_t*)&b;
    return (uint32_t)ua | ((uint32_t)ub << 16);
}
__global__ void split2h(const float* __restrict__ x,
                        __half* __restrict__ o0, __half* __restrict__ o1)
{
    const size_t i = (size_t)blockIdx.x * blockDim.x + threadIdx.x;
    float4 v = ((const float4*)x)[i];
    __half hx = __float2half_rn(v.x), hy = __float2half_rn(v.y);
    __half hz = __float2half_rn(v.z), hw = __float2half_rn(v.w);
    __half lx = __float2half_rn(v.x - __half2float(hx));
    __half ly = __float2half_rn(v.y - __half2float(hy));
    __half lz = __float2half_rn(v.z - __half2float(hz));
    __half lw = __float2half_rn(v.w - __half2float(hw));
    ((uint2*)o0)[i] = make_uint2(packh(hx, hy), packh(hz, hw));
    ((uint2*)o1)[i] = make_uint2(packh(lx, ly), packh(lz, lw));
}

// ---------------------------------------------------------------------------
// Rotated bias: b'[o] = sum_k R[k][o] * bias[k]
// ---------------------------------------------------------------------------
__global__ void rot_bias_kernel(const float* __restrict__ R,
                                const float* __restrict__ bias,
                                float* __restrict__ out)
{
    const int o = blockIdx.x * blockDim.x + threadIdx.x;
    if (o >= DOUT) return;
    float acc = 0.0f;
    for (int k = 0; k < KR; k++)
        acc = fmaf(R[(size_t)k * DOUT + o], bias[k], acc);
    out[o] = acc;
}

// ---------------------------------------------------------------------------
// Per-row max(|W'|) -> quant scale
// ---------------------------------------------------------------------------
__device__ __forceinline__ float block_reduce_max(float v) {
    __shared__ float sh[32];
    int lane = threadIdx.x & 31;
    int wid  = threadIdx.x >> 5;
    #pragma unroll
    for (int o = 16; o; o >>= 1) v = fmaxf(v, __shfl_xor_sync(0xffffffffu, v, o));
    if (lane == 0) sh[wid] = v;
    __syncthreads();
    int nw = blockDim.x >> 5;
    v = (threadIdx.x < (unsigned)nw) ? sh[threadIdx.x] : 0.0f;
    if (wid == 0) {
        #pragma unroll
        for (int o = 16; o; o >>= 1) v = fmaxf(v, __shfl_xor_sync(0xffffffffu, v, o));
    }
    if (threadIdx.x == 0) sh[0] = v;
    __syncthreads();
    return sh[0];
}
__global__ void wrowmax_kernel(const float* __restrict__ W, float* __restrict__ scale)
{
    const int row = blockIdx.x;
    const float* p = W + (size_t)row * DIN;
    float m = 0.0f;
    for (int i = threadIdx.x * 4; i < DIN; i += blockDim.x * 4) {
        float4 v = *(const float4*)&p[i];
        m = fmaxf(m, fmaxf(fmaxf(fabsf(v.x), fabsf(v.y)), fmaxf(fabsf(v.z), fabsf(v.w))));
    }
    m = block_reduce_max(m);
    if (threadIdx.x == 0)
        scale[row] = fmaxf(__fdiv_rn(m, 127.0f), 1e-8f);
}

// ---------------------------------------------------------------------------
// 8-bit fake-quant to fp16 integers (exact): q = clamp(rint(W/s_o))
// ---------------------------------------------------------------------------
__global__ void quant_h_kernel(const float* __restrict__ W,
                               const float* __restrict__ scale,
                               __half* __restrict__ q)
{
    const size_t idx4 = (size_t)blockIdx.x * blockDim.x + threadIdx.x;
    const int row = (int)(idx4 / (DIN / 4));
    const float s = scale[row];
    float4 v = ((const float4*)W)[idx4];
    float qx = fminf(fmaxf(rintf(__fdiv_rn(v.x, s)), -128.0f), 127.0f);
    float qy = fminf(fmaxf(rintf(__fdiv_rn(v.y, s)), -128.0f), 127.0f);
    float qz = fminf(fmaxf(rintf(__fdiv_rn(v.z, s)), -128.0f), 127.0f);
    float qw = fminf(fmaxf(rintf(__fdiv_rn(v.w, s)), -128.0f), 127.0f);
    ((uint2*)q)[idx4] = make_uint2(
        packh(__float2half_rn(qx), __float2half_rn(qy)),
        packh(__float2half_rn(qz), __float2half_rn(qw)));
}

// ---------------------------------------------------------------------------
// 16-bit per-token fake-quant, in place
// ---------------------------------------------------------------------------
__global__ void out_quant_kernel(float* __restrict__ out)
{
    const int s = blockIdx.x;
    float* p = out + (size_t)s * DOUT;
    float m = 0.0f;
    for (int i = threadIdx.x * 4; i < DOUT; i += blockDim.x * 4) {
        float4 v = *(const float4*)&p[i];
        m = fmaxf(m, fmaxf(fmaxf(fabsf(v.x), fabsf(v.y)), fmaxf(fabsf(v.z), fabsf(v.w))));
    }
    m = block_reduce_max(m);
    const float sc = fmaxf(__fdiv_rn(m, 32767.0f), 1e-8f);
    for (int i = threadIdx.x * 4; i < DOUT; i += blockDim.x * 4) {
        float4 v = *(const float4*)&p[i];
        v.x = fminf(fmaxf(rintf(__fdiv_rn(v.x, sc)), -32768.0f), 32767.0f) * sc;
        v.y = fminf(fmaxf(rintf(__fdiv_rn(v.y, sc)), -32768.0f), 32767.0f) * sc;
        v.z = fminf(fmaxf(rintf(__fdiv_rn(v.z, sc)), -32768.0f), 32767.0f) * sc;
        v.w = fminf(fmaxf(rintf(__fdiv_rn(v.w, sc)), -32768.0f), 32767.0f) * sc;
        *(float4*)&p[i] = v;
    }
}

// ---------------------------------------------------------------------------
// Launch
// ---------------------------------------------------------------------------
extern "C" void kernel_launch(void* const* d_in, const int* in_sizes, int n_in,
                              void* d_out, int out_size)
{
    const float* d_x = (const float*)d_in[0];
    const float* d_w = (const float*)d_in[1];
    const float* d_b = (const float*)d_in[2];
    const float* d_S = (const float*)d_in[3];
    const float* d_R = (const float*)d_in[4];
    float*       d_o = (float*)d_out;

    float *gW, *gws, *gbias;
    __half *gQ, *gA0, *gA1, *gB0, *gB1, *gX0, *gX1;
    cudaGetSymbolAddress((void**)&gW,   g_W);
    cudaGetSymbolAddress((void**)&gQ,   g_Q);
    cudaGetSymbolAddress((void**)&gA0,  g_A0);
    cudaGetSymbolAddress((void**)&gA1,  g_A1);
    cudaGetSymbolAddress((void**)&gB0,  g_B0);
    cudaGetSymbolAddress((void**)&gB1,  g_B1);
    cudaGetSymbolAddress((void**)&gX0,  g_X0);
    cudaGetSymbolAddress((void**)&gX1,  g_X1);
    cudaGetSymbolAddress((void**)&gws,  g_wscale);
    cudaGetSymbolAddress((void**)&gbias, g_bias);

    cudaFuncSetAttribute(gemm_mma, cudaFuncAttributeMaxDynamicSharedMemorySize, SMEM_DYN);

    // 1) rotated bias
    rot_bias_kernel<<<DOUT / 256, 256>>>(d_R, d_b, gbias);

    // 2) prep splits (pre-scaled by 2^6 each so lo stays in fp16 normal range)
    tsplit2h<<<dim3(DOUT / 32, KR / 32), dim3(32, 8)>>>(d_R, KR, DOUT, nullptr, 64.0f, gA0, gA1);
    tsplit2h<<<dim3(DIN / 32, KR / 32),  dim3(32, 8)>>>(d_w, KR, DIN,  d_S,    64.0f, gB0, gB1);
    split2h<<<(int)((size_t)SEQ * DIN / 4 / 256), 256>>>(d_x, gX0, gX1);

    // 3) GEMM1: W' = R^T (weight*S), 3-term fp16 split, alpha = 2^-12 un-scale
    {
        TermsH t;
        t.A[0] = gA0; t.B[0] = gB0;
        t.A[1] = gA0; t.B[1] = gB1;
        t.A[2] = gA1; t.B[2] = gB0;
        dim3 grid(DOUT / 128, DIN / 256);
        gemm_mma<<<grid, 512, SMEM_DYN>>>(t, 3, KR, gW, DIN, 1.0f / 4096.0f, nullptr, nullptr);
    }

    // 4) weight quant scale + quantize to fp16 ints
    wrowmax_kernel<<<DOUT, 256>>>(gW, gws);
    quant_h_kernel<<<(int)((size_t)DOUT * DIN / 4 / 256), 256>>>(gW, gws, gQ);

    // 5) GEMM2: out = (x @ q^T) * s_o + b'_o, 2-term x split (q exact in fp16)
    {
        TermsH t;
        t.A[0] = gX0; t.B[0] = gQ;
        t.A[1] = gX1; t.B[1] = gQ;
        t.A[2] = nullptr; t.B[2] = nullptr;
        dim3 grid(SEQ / 128, DOUT / 256);
        gemm_mma<<<grid, 512, SMEM_DYN>>>(t, 2, DIN, d_o, DOUT, 1.0f, gws, gbias);
    }

    // 6) 16-bit per-token fake-quant in place
    out_quant_kernel<<<SEQ, 256>>>(d_o);
}

// round 10
// speedup vs baseline: 1.3570x; 1.3355x over previous
#include <cuda_runtime.h>
#include <cuda_fp16.h>
#include <math.h>
#include <stdint.h>

// Problem dimensions (fixed)
#define SEQ   2048
#define DIN   11008
#define DOUT  4096
#define KR    4096

// ---------------------------------------------------------------------------
// Scratch (__device__ globals; no cudaMalloc allowed)
// ---------------------------------------------------------------------------
__device__ float  g_W [(size_t)DOUT * DIN];   // W' fp32 [o][i]
__device__ int8_t g_Q [(size_t)DOUT * DIN];   // quantized weights int8 [o][i]
__device__ __half g_A0[(size_t)DOUT * KR];    // (R^T * 64) hi  [o][k]
__device__ __half g_A1[(size_t)DOUT * KR];    // lo
__device__ __half g_B0[(size_t)DIN  * KR];    // ((w*S)^T * 64) hi [i][k]
__device__ __half g_B1[(size_t)DIN  * KR];    // lo
__device__ int8_t g_Xh[(size_t)SEQ  * DIN];   // x int16-hi byte [s][i]
__device__ int8_t g_Xl[(size_t)SEQ  * DIN];   // x int16-lo byte [s][i]
__device__ float  g_xs [SEQ];                 // per-token x scale
__device__ float  g_xsi[SEQ];                 // 1/scale
__device__ float  g_wscale[DOUT];
__device__ float  g_bias  [DOUT];

// ---------------------------------------------------------------------------
// PTX helpers
// ---------------------------------------------------------------------------
__device__ __forceinline__ uint32_t smem_u32(const void* p) {
    return (uint32_t)__cvta_generic_to_shared(p);
}
__device__ __forceinline__ void cp16(uint32_t s, const void* g) {
    asm volatile("cp.async.cg.shared.global [%0], [%1], 16;\n" :: "r"(s), "l"(g));
}
__device__ __forceinline__ void cp_commit() {
    asm volatile("cp.async.commit_group;" ::: "memory");
}
template<int N>
__device__ __forceinline__ void cp_wait() {
    asm volatile("cp.async.wait_group %0;" :: "n"(N) : "memory");
}
__device__ __forceinline__ void ldm4(uint32_t* r, uint32_t addr) {
    asm volatile("ldmatrix.sync.aligned.m8n8.x4.shared.b16 {%0,%1,%2,%3}, [%4];"
        : "=r"(r[0]), "=r"(r[1]), "=r"(r[2]), "=r"(r[3]) : "r"(addr));
}
__device__ __forceinline__ void mma16816(float* d, const uint32_t* a, uint32_t b0, uint32_t b1) {
    asm volatile("mma.sync.aligned.m16n8k16.row.col.f32.f16.f16.f32 "
        "{%0,%1,%2,%3}, {%4,%5,%6,%7}, {%8,%9}, {%0,%1,%2,%3};"
        : "+f"(d[0]), "+f"(d[1]), "+f"(d[2]), "+f"(d[3])
        : "r"(a[0]), "r"(a[1]), "r"(a[2]), "r"(a[3]), "r"(b0), "r"(b1));
}
__device__ __forceinline__ void mma_s8(int* d, const uint32_t* a, uint32_t b0, uint32_t b1) {
    asm volatile("mma.sync.aligned.m16n8k32.row.col.s32.s8.s8.s32 "
        "{%0,%1,%2,%3}, {%4,%5,%6,%7}, {%8,%9}, {%0,%1,%2,%3};"
        : "+r"(d[0]), "+r"(d[1]), "+r"(d[2]), "+r"(d[3])
        : "r"(a[0]), "r"(a[1]), "r"(a[2]), "r"(a[3]), "r"(b0), "r"(b1));
}

// ---------------------------------------------------------------------------
// fp16 GEMM (proven 4618us config): C = alpha * sum_t A_t @ B_t^T  (+epi)
// Tile 128x128x32, 256 threads (2x4 warps of 64x32), 4-stage cp.async.
// Smem swizzle: 16B chunk c at row r stored at c ^ ((r>>1)&3).
// ---------------------------------------------------------------------------
struct TermsH { const __half* A[3]; const __half* B[3]; };

#define STAGES   4
#define SM_STAGE 16384
#define SMEM_DYN (STAGES * SM_STAGE + 1024)

__global__ __launch_bounds__(256)
void gemm_mma(TermsH t, int nT, int K, float* __restrict__ C, int ldc, float alpha)
{
    extern __shared__ char raw[];
    const uint32_t base = (smem_u32(raw) + 1023u) & ~1023u;

    const int tid  = threadIdx.x;
    const int lane = tid & 31, wid = tid >> 5;
    const int wr   = wid & 1, wc = wid >> 1;
    const int m0   = blockIdx.x * 128, n0 = blockIdx.y * 128;

    uint32_t so[2]; uint32_t go[2];
    #pragma unroll
    for (int j = 0; j < 2; j++) {
        int ch = tid + j * 256;
        int r = ch >> 2, c = ch & 3;
        so[j] = (uint32_t)(r * 64 + ((c ^ ((r >> 1) & 3)) << 4));
        go[j] = (uint32_t)(r * K + c * 8);
    }

    uint32_t aoff[2][4], boff[2][2];
    #pragma unroll
    for (int ks = 0; ks < 2; ks++) {
        #pragma unroll
        for (int mf = 0; mf < 4; mf++) {
            int r = wr * 64 + mf * 16 + (lane & 15);
            int c = ks * 2 + (lane >> 4);
            aoff[ks][mf] = (uint32_t)(r * 64 + ((c ^ ((r >> 1) & 3)) << 4));
        }
        #pragma unroll
        for (int nf = 0; nf < 2; nf++) {
            int r = wc * 32 + nf * 16 + (lane & 7) + ((lane >> 4) << 3);
            int c = ks * 2 + ((lane >> 3) & 1);
            boff[ks][nf] = (uint32_t)(r * 64 + ((c ^ ((r >> 1) & 3)) << 4));
        }
    }

    const int kpt   = K >> 5;
    const int total = nT * kpt;
    int lt = 0, lk = 0;
    auto issue = [&](int stage) {
        const __half* ga = t.A[lt] + (size_t)m0 * K + lk * 32;
        const __half* gb = t.B[lt] + (size_t)n0 * K + lk * 32;
        const uint32_t sa = base + stage * SM_STAGE;
        const uint32_t sb = sa + 8192;
        #pragma unroll
        for (int j = 0; j < 2; j++) {
            cp16(sa + so[j], ga + go[j]);
            cp16(sb + so[j], gb + go[j]);
        }
        if (++lk == kpt) { lk = 0; ++lt; }
    };

    float acc[4][4][4];
    #pragma unroll
    for (int i = 0; i < 4; i++)
        #pragma unroll
        for (int j = 0; j < 4; j++)
            #pragma unroll
            for (int k = 0; k < 4; k++) acc[i][j][k] = 0.0f;

    #pragma unroll
    for (int s = 0; s < STAGES - 1; s++) {
        if (s < total) issue(s);
        cp_commit();
    }

    for (int i = 0; i < total; i++) {
        cp_wait<STAGES - 2>();
        __syncthreads();
        const int ns = i + STAGES - 1;
        if (ns < total) issue(ns & 3);
        cp_commit();

        const uint32_t sa = base + (i & 3) * SM_STAGE;
        const uint32_t sb = sa + 8192;

        uint32_t af[2][4][4], bf[2][2][4];
        #pragma unroll
        for (int ks = 0; ks < 2; ks++) {
            #pragma unroll
            for (int mf = 0; mf < 4; mf++) ldm4(af[ks][mf], sa + aoff[ks][mf]);
            #pragma unroll
            for (int np = 0; np < 2; np++) ldm4(bf[ks][np], sb + boff[ks][np]);
        }
        #pragma unroll
        for (int ks = 0; ks < 2; ks++)
            #pragma unroll
            for (int mf = 0; mf < 4; mf++)
                #pragma unroll
                for (int np = 0; np < 2; np++) {
                    mma16816(acc[mf][np * 2],     af[ks][mf], bf[ks][np][0], bf[ks][np][1]);
                    mma16816(acc[mf][np * 2 + 1], af[ks][mf], bf[ks][np][2], bf[ks][np][3]);
                }
    }

    const int ln4 = lane >> 2, lq = lane & 3;
    #pragma unroll
    for (int mf = 0; mf < 4; mf++) {
        #pragma unroll
        for (int h = 0; h < 2; h++) {
            const int row = m0 + wr * 64 + mf * 16 + ln4 + h * 8;
            float* crow = C + (size_t)row * ldc;
            #pragma unroll
            for (int nf = 0; nf < 4; nf++) {
                const int col = n0 + wc * 32 + nf * 8 + lq * 2;
                *(float2*)&crow[col] = make_float2(acc[mf][nf][h * 2] * alpha,
                                                   acc[mf][nf][h * 2 + 1] * alpha);
            }
        }
    }
}

// ---------------------------------------------------------------------------
// int8 GEMM (GEMM2): out[s][o] = ((256*Xh + Xl) @ Q^T) * rs[s]*cs[o] + cb[o]
// Tile 128x128, BK=64 bytes, 256 threads (2x4 warps, warp tile 64x32),
// 4-stage cp.async. Exact s32 accumulation; acc <<= 8 at the hi/lo boundary.
// ---------------------------------------------------------------------------
__global__ __launch_bounds__(256)
void gemm_s8(const int8_t* __restrict__ Xh, const int8_t* __restrict__ Xl,
             const int8_t* __restrict__ Q, int K,
             float* __restrict__ C, int ldc,
             const float* __restrict__ rs,
             const float* __restrict__ cs, const float* __restrict__ cb)
{
    extern __shared__ char raw[];
    const uint32_t base = (smem_u32(raw) + 1023u) & ~1023u;

    const int tid  = threadIdx.x;
    const int lane = tid & 31, wid = tid >> 5;
    const int wr   = wid & 1, wc = wid >> 1;
    const int m0   = blockIdx.x * 128, n0 = blockIdx.y * 128;

    // loader: 512 16B chunks per matrix (128 rows x 64B), 2/thread
    uint32_t so[2]; uint32_t go[2];
    #pragma unroll
    for (int j = 0; j < 2; j++) {
        int ch = tid + j * 256;
        int r = ch >> 2, c = ch & 3;
        so[j] = (uint32_t)(r * 64 + ((c ^ ((r >> 1) & 3)) << 4));
        go[j] = (uint32_t)(r * K + c * 16);           // bytes
    }

    // ldmatrix offsets. A tiles: (m0-7,klo16B),(m8-15,klo),(m0-7,khi),(m8-15,khi)
    // B tiles:                   (n0-7,klo),(n8-15,klo),(n0-7,khi),(n8-15,khi)
    // ks selects 32-byte half of the 64-byte stage row.
    uint32_t aoff[2][4], boff[2][2];
    #pragma unroll
    for (int ks = 0; ks < 2; ks++) {
        #pragma unroll
        for (int mf = 0; mf < 4; mf++) {
            int r = wr * 64 + mf * 16 + (lane & 15);
            int c = ks * 2 + (lane >> 4);
            aoff[ks][mf] = (uint32_t)(r * 64 + ((c ^ ((r >> 1) & 3)) << 4));
        }
        #pragma unroll
        for (int np = 0; np < 2; np++) {
            int r = wc * 32 + np * 16 + (lane & 15);
            int c = ks * 2 + (lane >> 4);
            boff[ks][np] = (uint32_t)(r * 64 + ((c ^ ((r >> 1) & 3)) << 4));
        }
    }

    const int kpt   = K >> 6;                         // 64 bytes per stage
    const int total = 2 * kpt;                        // hi term then lo term
    int lt = 0, lk = 0;
    const int8_t* Aplanes[2] = { Xh, Xl };
    auto issue = [&](int stage) {
        const int8_t* ga = Aplanes[lt] + (size_t)m0 * K + lk * 64;
        const int8_t* gb = Q           + (size_t)n0 * K + lk * 64;
        const uint32_t sa = base + stage * SM_STAGE;
        const uint32_t sb = sa + 8192;
        #pragma unroll
        for (int j = 0; j < 2; j++) {
            cp16(sa + so[j], ga + go[j]);
            cp16(sb + so[j], gb + go[j]);
        }
        if (++lk == kpt) { lk = 0; ++lt; }
    };

    int acc[4][4][4];
    #pragma unroll
    for (int i = 0; i < 4; i++)
        #pragma unroll
        for (int j = 0; j < 4; j++)
            #pragma unroll
            for (int k = 0; k < 4; k++) acc[i][j][k] = 0;

    #pragma unroll
    for (int s = 0; s < STAGES - 1; s++) {
        if (s < total) issue(s);
        cp_commit();
    }

    for (int i = 0; i < total; i++) {
        cp_wait<STAGES - 2>();
        __syncthreads();
        const int ns = i + STAGES - 1;
        if (ns < total) issue(ns & 3);
        cp_commit();

        const uint32_t sa = base + (i & 3) * SM_STAGE;
        const uint32_t sb = sa + 8192;

        #pragma unroll
        for (int ks = 0; ks < 2; ks++) {
            uint32_t af[4][4], bf[2][4];
            #pragma unroll
            for (int mf = 0; mf < 4; mf++) ldm4(af[mf], sa + aoff[ks][mf]);
            #pragma unroll
            for (int np = 0; np < 2; np++) ldm4(bf[np], sb + boff[ks][np]);
            // b regs: r0=(n0-7,klo16) r1=(n8-15,klo16) r2=(n0-7,khi16) r3=(n8-15,khi16)
            #pragma unroll
            for (int mf = 0; mf < 4; mf++)
                #pragma unroll
                for (int np = 0; np < 2; np++) {
                    mma_s8(acc[mf][np * 2],     af[mf], bf[np][0], bf[np][2]);
                    mma_s8(acc[mf][np * 2 + 1], af[mf], bf[np][1], bf[np][3]);
                }
        }

        if (i == kpt - 1) {                           // hi term done -> scale by 256
            #pragma unroll
            for (int a2 = 0; a2 < 4; a2++)
                #pragma unroll
                for (int b2 = 0; b2 < 4; b2++)
                    #pragma unroll
                    for (int c2 = 0; c2 < 4; c2++) acc[a2][b2][c2] <<= 8;
        }
    }

    const int ln4 = lane >> 2, lq = lane & 3;
    #pragma unroll
    for (int mf = 0; mf < 4; mf++) {
        #pragma unroll
        for (int h = 0; h < 2; h++) {
            const int row = m0 + wr * 64 + mf * 16 + ln4 + h * 8;
            const float srow = __ldg(&rs[row]);
            float* crow = C + (size_t)row * ldc;
            #pragma unroll
            for (int nf = 0; nf < 4; nf++) {
                const int col = n0 + wc * 32 + nf * 8 + lq * 2;
                float v0 = (float)acc[mf][nf][h * 2]     * (srow * __ldg(&cs[col]))     + __ldg(&cb[col]);
                float v1 = (float)acc[mf][nf][h * 2 + 1] * (srow * __ldg(&cs[col + 1])) + __ldg(&cb[col + 1]);
                *(float2*)&crow[col] = make_float2(v0, v1);
            }
        }
    }
}

// ---------------------------------------------------------------------------
// Prep: transpose + pre-scale + 2-way fp16 split (for GEMM1 operands)
// ---------------------------------------------------------------------------
__global__ void tsplit2h(const float* __restrict__ src, int rows, int cols,
                         const float* __restrict__ colScale, float mul,
                         __half* __restrict__ o0, __half* __restrict__ o1)
{
    __shared__ float tsh[32][33];
    const int c0 = blockIdx.x * 32, r0 = blockIdx.y * 32;
    #pragma unroll
    for (int rr = threadIdx.y; rr < 32; rr += 8)
        tsh[rr][threadIdx.x] = src[(size_t)(r0 + rr) * cols + c0 + threadIdx.x];
    __syncthreads();
    #pragma unroll
    for (int cc = threadIdx.y; cc < 32; cc += 8) {
        const int c = c0 + cc;
        float v = tsh[threadIdx.x][cc] * mul;
        if (colScale) v *= colScale[c];
        __half hi = __float2half_rn(v);
        __half lo = __float2half_rn(v - __half2float(hi));
        const size_t off = (size_t)c * rows + r0 + threadIdx.x;
        o0[off] = hi; o1[off] = lo;
    }
}

// ---------------------------------------------------------------------------
// Block reduce (max)
// ---------------------------------------------------------------------------
__device__ __forceinline__ float block_reduce_max(float v) {
    __shared__ float sh[32];
    int lane = threadIdx.x & 31;
    int wid  = threadIdx.x >> 5;
    #pragma unroll
    for (int o = 16; o; o >>= 1) v = fmaxf(v, __shfl_xor_sync(0xffffffffu, v, o));
    if (lane == 0) sh[wid] = v;
    __syncthreads();
    int nw = blockDim.x >> 5;
    v = (threadIdx.x < (unsigned)nw) ? sh[threadIdx.x] : 0.0f;
    if (wid == 0) {
        #pragma unroll
        for (int o = 16; o; o >>= 1) v = fmaxf(v, __shfl_xor_sync(0xffffffffu, v, o));
    }
    if (threadIdx.x == 0) sh[0] = v;
    __syncthreads();
    return sh[0];
}

// ---------------------------------------------------------------------------
// Per-token x scale: s = max|x_row| / 32512  (keeps int16 split hi in [-127,127])
// ---------------------------------------------------------------------------
__global__ void xscale_kernel(const float* __restrict__ x,
                              float* __restrict__ s, float* __restrict__ si)
{
    const int row = blockIdx.x;
    const float4* p = (const float4*)(x + (size_t)row * DIN);
    float m = 0.0f;
    for (int i = threadIdx.x; i < DIN / 4; i += blockDim.x) {
        float4 v = p[i];
        m = fmaxf(m, fmaxf(fmaxf(fabsf(v.x), fabsf(v.y)), fmaxf(fabsf(v.z), fabsf(v.w))));
    }
    m = block_reduce_max(m);
    if (threadIdx.x == 0) {
        float sc = fmaxf(__fdiv_rn(m, 32512.0f), 1e-20f);
        s[row]  = sc;
        si[row] = __fdiv_rn(1.0f, sc);
    }
}

// ---------------------------------------------------------------------------
// x -> int16 -> (hi, lo) int8 planes:  v = rint(x/s), v = 256*h + l
// ---------------------------------------------------------------------------
__global__ void xsplit8_kernel(const float* __restrict__ x,
                               const float* __restrict__ si,
                               int8_t* __restrict__ oh, int8_t* __restrict__ ol)
{
    const size_t idx4 = (size_t)blockIdx.x * blockDim.x + threadIdx.x;
    const int row = (int)(idx4 / (DIN / 4));
    const float inv = si[row];
    float4 v = ((const float4*)x)[idx4];
    int   iv[4];
    iv[0] = (int)fminf(fmaxf(rintf(v.x * inv), -32512.0f), 32512.0f);
    iv[1] = (int)fminf(fmaxf(rintf(v.y * inv), -32512.0f), 32512.0f);
    iv[2] = (int)fminf(fmaxf(rintf(v.z * inv), -32512.0f), 32512.0f);
    iv[3] = (int)fminf(fmaxf(rintf(v.w * inv), -32512.0f), 32512.0f);
    uint32_t hw = 0, lw = 0;
    #pragma unroll
    for (int j = 0; j < 4; j++) {
        int h = (iv[j] + 128) >> 8;
        int l = iv[j] - (h << 8);
        hw |= ((uint32_t)(uint8_t)(int8_t)h) << (j * 8);
        lw |= ((uint32_t)(uint8_t)(int8_t)l) << (j * 8);
    }
    ((uint32_t*)oh)[idx4] = hw;
    ((uint32_t*)ol)[idx4] = lw;
}

// ---------------------------------------------------------------------------
// Rotated bias: b'[o] = sum_k R[k][o] * bias[k]
// ---------------------------------------------------------------------------
__global__ void rot_bias_kernel(const float* __restrict__ R,
                                const float* __restrict__ bias,
                                float* __restrict__ out)
{
    const int o = blockIdx.x * blockDim.x + threadIdx.x;
    if (o >= DOUT) return;
    float acc = 0.0f;
    for (int k = 0; k < KR; k++)
        acc = fmaf(R[(size_t)k * DOUT + o], bias[k], acc);
    out[o] = acc;
}

// ---------------------------------------------------------------------------
// Per-row max(|W'|) -> quant scale
// ---------------------------------------------------------------------------
__global__ void wrowmax_kernel(const float* __restrict__ W, float* __restrict__ scale)
{
    const int row = blockIdx.x;
    const float* p = W + (size_t)row * DIN;
    float m = 0.0f;
    for (int i = threadIdx.x * 4; i < DIN; i += blockDim.x * 4) {
        float4 v = *(const float4*)&p[i];
        m = fmaxf(m, fmaxf(fmaxf(fabsf(v.x), fabsf(v.y)), fmaxf(fabsf(v.z), fabsf(v.w))));
    }
    m = block_reduce_max(m);
    if (threadIdx.x == 0)
        scale[row] = fmaxf(__fdiv_rn(m, 127.0f), 1e-8f);
}

// ---------------------------------------------------------------------------
// 8-bit fake-quant to int8: q = clamp(rint(W/s_o))
// ---------------------------------------------------------------------------
__global__ void quant_s8_kernel(const float* __restrict__ W,
                                const float* __restrict__ scale,
                                int8_t* __restrict__ q)
{
    const size_t idx4 = (size_t)blockIdx.x * blockDim.x + threadIdx.x;
    const int row = (int)(idx4 / (DIN / 4));
    const float s = scale[row];
    float4 v = ((const float4*)W)[idx4];
    int qx = (int)fminf(fmaxf(rintf(__fdiv_rn(v.x, s)), -128.0f), 127.0f);
    int qy = (int)fminf(fmaxf(rintf(__fdiv_rn(v.y, s)), -128.0f), 127.0f);
    int qz = (int)fminf(fmaxf(rintf(__fdiv_rn(v.z, s)), -128.0f), 127.0f);
    int qw = (int)fminf(fmaxf(rintf(__fdiv_rn(v.w, s)), -128.0f), 127.0f);
    uint32_t w = ((uint32_t)(uint8_t)(int8_t)qx)
               | ((uint32_t)(uint8_t)(int8_t)qy << 8)
               | ((uint32_t)(uint8_t)(int8_t)qz << 16)
               | ((uint32_t)(uint8_t)(int8_t)qw << 24);
    ((uint32_t*)q)[idx4] = w;
}

// ---------------------------------------------------------------------------
// 16-bit per-token fake-quant, in place
// ---------------------------------------------------------------------------
__global__ void out_quant_kernel(float* __restrict__ out)
{
    const int s = blockIdx.x;
    float* p = out + (size_t)s * DOUT;
    float m = 0.0f;
    for (int i = threadIdx.x * 4; i < DOUT; i += blockDim.x * 4) {
        float4 v = *(const float4*)&p[i];
        m = fmaxf(m, fmaxf(fmaxf(fabsf(v.x), fabsf(v.y)), fmaxf(fabsf(v.z), fabsf(v.w))));
    }
    m = block_reduce_max(m);
    const float sc = fmaxf(__fdiv_rn(m, 32767.0f), 1e-8f);
    for (int i = threadIdx.x * 4; i < DOUT; i += blockDim.x * 4) {
        float4 v = *(const float4*)&p[i];
        v.x = fminf(fmaxf(rintf(__fdiv_rn(v.x, sc)), -32768.0f), 32767.0f) * sc;
        v.y = fminf(fmaxf(rintf(__fdiv_rn(v.y, sc)), -32768.0f), 32767.0f) * sc;
        v.z = fminf(fmaxf(rintf(__fdiv_rn(v.z, sc)), -32768.0f), 32767.0f) * sc;
        v.w = fminf(fmaxf(rintf(__fdiv_rn(v.w, sc)), -32768.0f), 32767.0f) * sc;
        *(float4*)&p[i] = v;
    }
}

// ---------------------------------------------------------------------------
// Launch
// ---------------------------------------------------------------------------
extern "C" void kernel_launch(void* const* d_in, const int* in_sizes, int n_in,
                              void* d_out, int out_size)
{
    const float* d_x = (const float*)d_in[0];
    const float* d_w = (const float*)d_in[1];
    const float* d_b = (const float*)d_in[2];
    const float* d_S = (const float*)d_in[3];
    const float* d_R = (const float*)d_in[4];
    float*       d_o = (float*)d_out;

    float *gW, *gws, *gbias, *gxs, *gxsi;
    __half *gA0, *gA1, *gB0, *gB1;
    int8_t *gQ, *gXh, *gXl;
    cudaGetSymbolAddress((void**)&gW,   g_W);
    cudaGetSymbolAddress((void**)&gQ,   g_Q);
    cudaGetSymbolAddress((void**)&gA0,  g_A0);
    cudaGetSymbolAddress((void**)&gA1,  g_A1);
    cudaGetSymbolAddress((void**)&gB0,  g_B0);
    cudaGetSymbolAddress((void**)&gB1,  g_B1);
    cudaGetSymbolAddress((void**)&gXh,  g_Xh);
    cudaGetSymbolAddress((void**)&gXl,  g_Xl);
    cudaGetSymbolAddress((void**)&gxs,  g_xs);
    cudaGetSymbolAddress((void**)&gxsi, g_xsi);
    cudaGetSymbolAddress((void**)&gws,  g_wscale);
    cudaGetSymbolAddress((void**)&gbias, g_bias);

    cudaFuncSetAttribute(gemm_mma, cudaFuncAttributeMaxDynamicSharedMemorySize, SMEM_DYN);
    cudaFuncSetAttribute(gemm_s8,  cudaFuncAttributeMaxDynamicSharedMemorySize, SMEM_DYN);

    // 1) rotated bias
    rot_bias_kernel<<<DOUT / 256, 256>>>(d_R, d_b, gbias);

    // 2) prep: fp16 splits for GEMM1; int8 split of x for GEMM2
    tsplit2h<<<dim3(DOUT / 32, KR / 32), dim3(32, 8)>>>(d_R, KR, DOUT, nullptr, 64.0f, gA0, gA1);
    tsplit2h<<<dim3(DIN / 32, KR / 32),  dim3(32, 8)>>>(d_w, KR, DIN,  d_S,    64.0f, gB0, gB1);
    xscale_kernel<<<SEQ, 256>>>(d_x, gxs, gxsi);
    xsplit8_kernel<<<(int)((size_t)SEQ * DIN / 4 / 256), 256>>>(d_x, gxsi, gXh, gXl);

    // 3) GEMM1: W' = R^T (weight*S), 3-term fp16 split, alpha = 2^-12 un-scale
    {
        TermsH t;
        t.A[0] = gA0; t.B[0] = gB0;
        t.A[1] = gA0; t.B[1] = gB1;
        t.A[2] = gA1; t.B[2] = gB0;
        dim3 grid(DOUT / 128, DIN / 128);
        gemm_mma<<<grid, 256, SMEM_DYN>>>(t, 3, KR, gW, DIN, 1.0f / 4096.0f);
    }

    // 4) weight quant scale + quantize to int8
    wrowmax_kernel<<<DOUT, 256>>>(gW, gws);
    quant_s8_kernel<<<(int)((size_t)DOUT * DIN / 4 / 256), 256>>>(gW, gws, gQ);

    // 5) GEMM2 (int8, exact): out = (x16 @ q^T) * s_tok*s_o + b'
    {
        dim3 grid(SEQ / 128, DOUT / 128);
        gemm_s8<<<grid, 256, SMEM_DYN>>>(gXh, gXl, gQ, DIN, d_o, DOUT, gxs, gws, gbias);
    }

    // 6) 16-bit per-token fake-quant in place
    out_quant_kernel<<<SEQ, 256>>>(d_o);
}

// round 11
// speedup vs baseline: 1.3997x; 1.0315x over previous
#include <cuda_runtime.h>
#include <cuda_fp16.h>
#include <math.h>
#include <stdint.h>

// Problem dimensions (fixed)
#define SEQ   2048
#define DIN   11008
#define DOUT  4096
#define KR    4096

// ---------------------------------------------------------------------------
// Scratch (__device__ globals; no cudaMalloc allowed)
// ---------------------------------------------------------------------------
__device__ float  g_W [(size_t)DOUT * DIN];   // W' fp32 [o][i]
__device__ int8_t g_Q [(size_t)DOUT * DIN];   // quantized weights int8 [o][i]
__device__ __half g_A0[(size_t)DOUT * KR];    // (R^T * 64) hi  [o][k]
__device__ __half g_A1[(size_t)DOUT * KR];    // lo
__device__ __half g_B0[(size_t)DIN  * KR];    // ((w*S)^T * 64) hi [i][k]
__device__ __half g_B1[(size_t)DIN  * KR];    // lo
__device__ int8_t g_Xh[(size_t)SEQ  * DIN];   // x int16-hi byte [s][i]
__device__ int8_t g_Xl[(size_t)SEQ  * DIN];   // x int16-lo byte [s][i]
__device__ float  g_xs [SEQ];                 // per-token x scale
__device__ float  g_xsi[SEQ];                 // 1/scale
__device__ float  g_wscale[DOUT];
__device__ float  g_bias  [DOUT];

// ---------------------------------------------------------------------------
// PTX helpers
// ---------------------------------------------------------------------------
__device__ __forceinline__ uint32_t smem_u32(const void* p) {
    return (uint32_t)__cvta_generic_to_shared(p);
}
__device__ __forceinline__ void cp16(uint32_t s, const void* g) {
    asm volatile("cp.async.cg.shared.global [%0], [%1], 16;\n" :: "r"(s), "l"(g));
}
__device__ __forceinline__ void cp_commit() {
    asm volatile("cp.async.commit_group;" ::: "memory");
}
template<int N>
__device__ __forceinline__ void cp_wait() {
    asm volatile("cp.async.wait_group %0;" :: "n"(N) : "memory");
}
__device__ __forceinline__ void ldm4(uint32_t* r, uint32_t addr) {
    asm volatile("ldmatrix.sync.aligned.m8n8.x4.shared.b16 {%0,%1,%2,%3}, [%4];"
        : "=r"(r[0]), "=r"(r[1]), "=r"(r[2]), "=r"(r[3]) : "r"(addr));
}
__device__ __forceinline__ void mma16816(float* d, const uint32_t* a, uint32_t b0, uint32_t b1) {
    asm volatile("mma.sync.aligned.m16n8k16.row.col.f32.f16.f16.f32 "
        "{%0,%1,%2,%3}, {%4,%5,%6,%7}, {%8,%9}, {%0,%1,%2,%3};"
        : "+f"(d[0]), "+f"(d[1]), "+f"(d[2]), "+f"(d[3])
        : "r"(a[0]), "r"(a[1]), "r"(a[2]), "r"(a[3]), "r"(b0), "r"(b1));
}
__device__ __forceinline__ void mma_s8(int* d, const uint32_t* a, uint32_t b0, uint32_t b1) {
    asm volatile("mma.sync.aligned.m16n8k32.row.col.s32.s8.s8.s32 "
        "{%0,%1,%2,%3}, {%4,%5,%6,%7}, {%8,%9}, {%0,%1,%2,%3};"
        : "+r"(d[0]), "+r"(d[1]), "+r"(d[2]), "+r"(d[3])
        : "r"(a[0]), "r"(a[1]), "r"(a[2]), "r"(a[3]), "r"(b0), "r"(b1));
}

// ---------------------------------------------------------------------------
// fp16 GEMM: C = alpha * sum_t A_t @ B_t^T
// Tile 128x128x32, 256 threads (2x4 warps of 64x32), 3-stage cp.async,
// 2 CTAs/SM (launch_bounds reg cap 128; per-ks fragment scope avoids spill).
// Smem swizzle: 16B chunk c at row r stored at c ^ ((r>>1)&3).
// ---------------------------------------------------------------------------
struct TermsH { const __half* A[3]; const __half* B[3]; };

#define STAGES   3
#define SM_STAGE 16384
#define SMEM_DYN (STAGES * SM_STAGE + 1024)

__global__ __launch_bounds__(256, 2)
void gemm_mma(TermsH t, int nT, int K, float* __restrict__ C, int ldc, float alpha)
{
    extern __shared__ char raw[];
    const uint32_t base = (smem_u32(raw) + 1023u) & ~1023u;

    const int tid  = threadIdx.x;
    const int lane = tid & 31, wid = tid >> 5;
    const int wr   = wid & 1, wc = wid >> 1;
    const int m0   = blockIdx.x * 128, n0 = blockIdx.y * 128;

    uint32_t so[2]; uint32_t go[2];
    #pragma unroll
    for (int j = 0; j < 2; j++) {
        int ch = tid + j * 256;
        int r = ch >> 2, c = ch & 3;
        so[j] = (uint32_t)(r * 64 + ((c ^ ((r >> 1) & 3)) << 4));
        go[j] = (uint32_t)(r * K + c * 8);
    }

    uint32_t aoff[2][4], boff[2][2];
    #pragma unroll
    for (int ks = 0; ks < 2; ks++) {
        #pragma unroll
        for (int mf = 0; mf < 4; mf++) {
            int r = wr * 64 + mf * 16 + (lane & 15);
            int c = ks * 2 + (lane >> 4);
            aoff[ks][mf] = (uint32_t)(r * 64 + ((c ^ ((r >> 1) & 3)) << 4));
        }
        #pragma unroll
        for (int nf = 0; nf < 2; nf++) {
            int r = wc * 32 + nf * 16 + (lane & 7) + ((lane >> 4) << 3);
            int c = ks * 2 + ((lane >> 3) & 1);
            boff[ks][nf] = (uint32_t)(r * 64 + ((c ^ ((r >> 1) & 3)) << 4));
        }
    }

    const int kpt   = K >> 5;
    const int total = nT * kpt;
    int lt = 0, lk = 0;
    auto issue = [&](int stage) {
        const __half* ga = t.A[lt] + (size_t)m0 * K + lk * 32;
        const __half* gb = t.B[lt] + (size_t)n0 * K + lk * 32;
        const uint32_t sa = base + stage * SM_STAGE;
        const uint32_t sb = sa + 8192;
        #pragma unroll
        for (int j = 0; j < 2; j++) {
            cp16(sa + so[j], ga + go[j]);
            cp16(sb + so[j], gb + go[j]);
        }
        if (++lk == kpt) { lk = 0; ++lt; }
    };

    float acc[4][4][4];
    #pragma unroll
    for (int i = 0; i < 4; i++)
        #pragma unroll
        for (int j = 0; j < 4; j++)
            #pragma unroll
            for (int k = 0; k < 4; k++) acc[i][j][k] = 0.0f;

    #pragma unroll
    for (int s = 0; s < STAGES - 1; s++) {
        if (s < total) issue(s);
        cp_commit();
    }

    int st_c = 0, st_l = STAGES - 1;
    for (int i = 0; i < total; i++) {
        cp_wait<STAGES - 2>();
        __syncthreads();
        if (i + STAGES - 1 < total) issue(st_l);
        cp_commit();
        if (++st_l == STAGES) st_l = 0;

        const uint32_t sa = base + st_c * SM_STAGE;
        const uint32_t sb = sa + 8192;
        if (++st_c == STAGES) st_c = 0;

        #pragma unroll
        for (int ks = 0; ks < 2; ks++) {
            uint32_t af[4][4], bf[2][4];
            #pragma unroll
            for (int mf = 0; mf < 4; mf++) ldm4(af[mf], sa + aoff[ks][mf]);
            #pragma unroll
            for (int np = 0; np < 2; np++) ldm4(bf[np], sb + boff[ks][np]);
            #pragma unroll
            for (int mf = 0; mf < 4; mf++)
                #pragma unroll
                for (int np = 0; np < 2; np++) {
                    mma16816(acc[mf][np * 2],     af[mf], bf[np][0], bf[np][1]);
                    mma16816(acc[mf][np * 2 + 1], af[mf], bf[np][2], bf[np][3]);
                }
        }
    }

    const int ln4 = lane >> 2, lq = lane & 3;
    #pragma unroll
    for (int mf = 0; mf < 4; mf++) {
        #pragma unroll
        for (int h = 0; h < 2; h++) {
            const int row = m0 + wr * 64 + mf * 16 + ln4 + h * 8;
            float* crow = C + (size_t)row * ldc;
            #pragma unroll
            for (int nf = 0; nf < 4; nf++) {
                const int col = n0 + wc * 32 + nf * 8 + lq * 2;
                *(float2*)&crow[col] = make_float2(acc[mf][nf][h * 2] * alpha,
                                                   acc[mf][nf][h * 2 + 1] * alpha);
            }
        }
    }
}

// ---------------------------------------------------------------------------
// int8 GEMM (GEMM2): out[s][o] = ((256*Xh + Xl) @ Q^T) * rs[s]*cs[o] + cb[o]
// Tile 128x128, BK=64 bytes, 256 threads, 3-stage cp.async, 2 CTAs/SM.
// Exact s32 accumulation; acc <<= 8 at the hi/lo term boundary.
// ---------------------------------------------------------------------------
__global__ __launch_bounds__(256, 2)
void gemm_s8(const int8_t* __restrict__ Xh, const int8_t* __restrict__ Xl,
             const int8_t* __restrict__ Q, int K,
             float* __restrict__ C, int ldc,
             const float* __restrict__ rs,
             const float* __restrict__ cs, const float* __restrict__ cb)
{
    extern __shared__ char raw[];
    const uint32_t base = (smem_u32(raw) + 1023u) & ~1023u;

    const int tid  = threadIdx.x;
    const int lane = tid & 31, wid = tid >> 5;
    const int wr   = wid & 1, wc = wid >> 1;
    const int m0   = blockIdx.x * 128, n0 = blockIdx.y * 128;

    uint32_t so[2]; uint32_t go[2];
    #pragma unroll
    for (int j = 0; j < 2; j++) {
        int ch = tid + j * 256;
        int r = ch >> 2, c = ch & 3;
        so[j] = (uint32_t)(r * 64 + ((c ^ ((r >> 1) & 3)) << 4));
        go[j] = (uint32_t)(r * K + c * 16);           // bytes
    }

    uint32_t aoff[2][4], boff[2][2];
    #pragma unroll
    for (int ks = 0; ks < 2; ks++) {
        #pragma unroll
        for (int mf = 0; mf < 4; mf++) {
            int r = wr * 64 + mf * 16 + (lane & 15);
            int c = ks * 2 + (lane >> 4);
            aoff[ks][mf] = (uint32_t)(r * 64 + ((c ^ ((r >> 1) & 3)) << 4));
        }
        #pragma unroll
        for (int np = 0; np < 2; np++) {
            int r = wc * 32 + np * 16 + (lane & 15);
            int c = ks * 2 + (lane >> 4);
            boff[ks][np] = (uint32_t)(r * 64 + ((c ^ ((r >> 1) & 3)) << 4));
        }
    }

    const int kpt   = K >> 6;                         // 64 bytes per stage
    const int total = 2 * kpt;                        // hi term then lo term
    int lt = 0, lk = 0;
    const int8_t* Aplanes[2] = { Xh, Xl };
    auto issue = [&](int stage) {
        const int8_t* ga = Aplanes[lt] + (size_t)m0 * K + lk * 64;
        const int8_t* gb = Q           + (size_t)n0 * K + lk * 64;
        const uint32_t sa = base + stage * SM_STAGE;
        const uint32_t sb = sa + 8192;
        #pragma unroll
        for (int j = 0; j < 2; j++) {
            cp16(sa + so[j], ga + go[j]);
            cp16(sb + so[j], gb + go[j]);
        }
        if (++lk == kpt) { lk = 0; ++lt; }
    };

    int acc[4][4][4];
    #pragma unroll
    for (int i = 0; i < 4; i++)
        #pragma unroll
        for (int j = 0; j < 4; j++)
            #pragma unroll
            for (int k = 0; k < 4; k++) acc[i][j][k] = 0;

    #pragma unroll
    for (int s = 0; s < STAGES - 1; s++) {
        if (s < total) issue(s);
        cp_commit();
    }

    int st_c = 0, st_l = STAGES - 1;
    for (int i = 0; i < total; i++) {
        cp_wait<STAGES - 2>();
        __syncthreads();
        if (i + STAGES - 1 < total) issue(st_l);
        cp_commit();
        if (++st_l == STAGES) st_l = 0;

        const uint32_t sa = base + st_c * SM_STAGE;
        const uint32_t sb = sa + 8192;
        if (++st_c == STAGES) st_c = 0;

        #pragma unroll
        for (int ks = 0; ks < 2; ks++) {
            uint32_t af[4][4], bf[2][4];
            #pragma unroll
            for (int mf = 0; mf < 4; mf++) ldm4(af[mf], sa + aoff[ks][mf]);
            #pragma unroll
            for (int np = 0; np < 2; np++) ldm4(bf[np], sb + boff[ks][np]);
            #pragma unroll
            for (int mf = 0; mf < 4; mf++)
                #pragma unroll
                for (int np = 0; np < 2; np++) {
                    mma_s8(acc[mf][np * 2],     af[mf], bf[np][0], bf[np][2]);
                    mma_s8(acc[mf][np * 2 + 1], af[mf], bf[np][1], bf[np][3]);
                }
        }

        if (i == kpt - 1) {                           // hi term done -> scale by 256
            #pragma unroll
            for (int a2 = 0; a2 < 4; a2++)
                #pragma unroll
                for (int b2 = 0; b2 < 4; b2++)
                    #pragma unroll
                    for (int c2 = 0; c2 < 4; c2++) acc[a2][b2][c2] <<= 8;
        }
    }

    const int ln4 = lane >> 2, lq = lane & 3;
    #pragma unroll
    for (int mf = 0; mf < 4; mf++) {
        #pragma unroll
        for (int h = 0; h < 2; h++) {
            const int row = m0 + wr * 64 + mf * 16 + ln4 + h * 8;
            const float srow = __ldg(&rs[row]);
            float* crow = C + (size_t)row * ldc;
            #pragma unroll
            for (int nf = 0; nf < 4; nf++) {
                const int col = n0 + wc * 32 + nf * 8 + lq * 2;
                float v0 = (float)acc[mf][nf][h * 2]     * (srow * __ldg(&cs[col]))     + __ldg(&cb[col]);
                float v1 = (float)acc[mf][nf][h * 2 + 1] * (srow * __ldg(&cs[col + 1])) + __ldg(&cb[col + 1]);
                *(float2*)&crow[col] = make_float2(v0, v1);
            }
        }
    }
}

// ---------------------------------------------------------------------------
// Prep: transpose + pre-scale + 2-way fp16 split (for GEMM1 operands)
// ---------------------------------------------------------------------------
__global__ void tsplit2h(const float* __restrict__ src, int rows, int cols,
                         const float* __restrict__ colScale, float mul,
                         __half* __restrict__ o0, __half* __restrict__ o1)
{
    __shared__ float tsh[32][33];
    const int c0 = blockIdx.x * 32, r0 = blockIdx.y * 32;
    #pragma unroll
    for (int rr = threadIdx.y; rr < 32; rr += 8)
        tsh[rr][threadIdx.x] = src[(size_t)(r0 + rr) * cols + c0 + threadIdx.x];
    __syncthreads();
    #pragma unroll
    for (int cc = threadIdx.y; cc < 32; cc += 8) {
        const int c = c0 + cc;
        float v = tsh[threadIdx.x][cc] * mul;
        if (colScale) v *= colScale[c];
        __half hi = __float2half_rn(v);
        __half lo = __float2half_rn(v - __half2float(hi));
        const size_t off = (size_t)c * rows + r0 + threadIdx.x;
        o0[off] = hi; o1[off] = lo;
    }
}

// ---------------------------------------------------------------------------
// Block reduce (max)
// ---------------------------------------------------------------------------
__device__ __forceinline__ float block_reduce_max(float v) {
    __shared__ float sh[32];
    int lane = threadIdx.x & 31;
    int wid  = threadIdx.x >> 5;
    #pragma unroll
    for (int o = 16; o; o >>= 1) v = fmaxf(v, __shfl_xor_sync(0xffffffffu, v, o));
    if (lane == 0) sh[wid] = v;
    __syncthreads();
    int nw = blockDim.x >> 5;
    v = (threadIdx.x < (unsigned)nw) ? sh[threadIdx.x] : 0.0f;
    if (wid == 0) {
        #pragma unroll
        for (int o = 16; o; o >>= 1) v = fmaxf(v, __shfl_xor_sync(0xffffffffu, v, o));
    }
    if (threadIdx.x == 0) sh[0] = v;
    __syncthreads();
    return sh[0];
}

// ---------------------------------------------------------------------------
// Per-token x scale: s = max|x_row| / 32512  (keeps int16 split hi in [-127,127])
// ---------------------------------------------------------------------------
__global__ void xscale_kernel(const float* __restrict__ x,
                              float* __restrict__ s, float* __restrict__ si)
{
    const int row = blockIdx.x;
    const float4* p = (const float4*)(x + (size_t)row * DIN);
    float m = 0.0f;
    for (int i = threadIdx.x; i < DIN / 4; i += blockDim.x) {
        float4 v = p[i];
        m = fmaxf(m, fmaxf(fmaxf(fabsf(v.x), fabsf(v.y)), fmaxf(fabsf(v.z), fabsf(v.w))));
    }
    m = block_reduce_max(m);
    if (threadIdx.x == 0) {
        float sc = fmaxf(__fdiv_rn(m, 32512.0f), 1e-20f);
        s[row]  = sc;
        si[row] = __fdiv_rn(1.0f, sc);
    }
}

// ---------------------------------------------------------------------------
// x -> int16 -> (hi, lo) int8 planes:  v = rint(x/s), v = 256*h + l
// ---------------------------------------------------------------------------
__global__ void xsplit8_kernel(const float* __restrict__ x,
                               const float* __restrict__ si,
                               int8_t* __restrict__ oh, int8_t* __restrict__ ol)
{
    const size_t idx4 = (size_t)blockIdx.x * blockDim.x + threadIdx.x;
    const int row = (int)(idx4 / (DIN / 4));
    const float inv = si[row];
    float4 v = ((const float4*)x)[idx4];
    int   iv[4];
    iv[0] = (int)fminf(fmaxf(rintf(v.x * inv), -32512.0f), 32512.0f);
    iv[1] = (int)fminf(fmaxf(rintf(v.y * inv), -32512.0f), 32512.0f);
    iv[2] = (int)fminf(fmaxf(rintf(v.z * inv), -32512.0f), 32512.0f);
    iv[3] = (int)fminf(fmaxf(rintf(v.w * inv), -32512.0f), 32512.0f);
    uint32_t hw = 0, lw = 0;
    #pragma unroll
    for (int j = 0; j < 4; j++) {
        int h = (iv[j] + 128) >> 8;
        int l = iv[j] - (h << 8);
        hw |= ((uint32_t)(uint8_t)(int8_t)h) << (j * 8);
        lw |= ((uint32_t)(uint8_t)(int8_t)l) << (j * 8);
    }
    ((uint32_t*)oh)[idx4] = hw;
    ((uint32_t*)ol)[idx4] = lw;
}

// ---------------------------------------------------------------------------
// Rotated bias: b'[o] = sum_k R[k][o] * bias[k]
// ---------------------------------------------------------------------------
__global__ void rot_bias_kernel(const float* __restrict__ R,
                                const float* __restrict__ bias,
                                float* __restrict__ out)
{
    const int o = blockIdx.x * blockDim.x + threadIdx.x;
    if (o >= DOUT) return;
    float acc = 0.0f;
    for (int k = 0; k < KR; k++)
        acc = fmaf(R[(size_t)k * DOUT + o], bias[k], acc);
    out[o] = acc;
}

// ---------------------------------------------------------------------------
// Per-row max(|W'|) -> quant scale
// ---------------------------------------------------------------------------
__global__ void wrowmax_kernel(const float* __restrict__ W, float* __restrict__ scale)
{
    const int row = blockIdx.x;
    const float* p = W + (size_t)row * DIN;
    float m = 0.0f;
    for (int i = threadIdx.x * 4; i < DIN; i += blockDim.x * 4) {
        float4 v = *(const float4*)&p[i];
        m = fmaxf(m, fmaxf(fmaxf(fabsf(v.x), fabsf(v.y)), fmaxf(fabsf(v.z), fabsf(v.w))));
    }
    m = block_reduce_max(m);
    if (threadIdx.x == 0)
        scale[row] = fmaxf(__fdiv_rn(m, 127.0f), 1e-8f);
}

// ---------------------------------------------------------------------------
// 8-bit fake-quant to int8: q = clamp(rint(W/s_o))
// ---------------------------------------------------------------------------
__global__ void quant_s8_kernel(const float* __restrict__ W,
                                const float* __restrict__ scale,
                                int8_t* __restrict__ q)
{
    const size_t idx4 = (size_t)blockIdx.x * blockDim.x + threadIdx.x;
    const int row = (int)(idx4 / (DIN / 4));
    const float s = scale[row];
    float4 v = ((const float4*)W)[idx4];
    int qx = (int)fminf(fmaxf(rintf(__fdiv_rn(v.x, s)), -128.0f), 127.0f);
    int qy = (int)fminf(fmaxf(rintf(__fdiv_rn(v.y, s)), -128.0f), 127.0f);
    int qz = (int)fminf(fmaxf(rintf(__fdiv_rn(v.z, s)), -128.0f), 127.0f);
    int qw = (int)fminf(fmaxf(rintf(__fdiv_rn(v.w, s)), -128.0f), 127.0f);
    uint32_t w = ((uint32_t)(uint8_t)(int8_t)qx)
               | ((uint32_t)(uint8_t)(int8_t)qy << 8)
               | ((uint32_t)(uint8_t)(int8_t)qz << 16)
               | ((uint32_t)(uint8_t)(int8_t)qw << 24);
    ((uint32_t*)q)[idx4] = w;
}

// ---------------------------------------------------------------------------
// 16-bit per-token fake-quant, in place
// ---------------------------------------------------------------------------
__global__ void out_quant_kernel(float* __restrict__ out)
{
    const int s = blockIdx.x;
    float* p = out + (size_t)s * DOUT;
    float m = 0.0f;
    for (int i = threadIdx.x * 4; i < DOUT; i += blockDim.x * 4) {
        float4 v = *(const float4*)&p[i];
        m = fmaxf(m, fmaxf(fmaxf(fabsf(v.x), fabsf(v.y)), fmaxf(fabsf(v.z), fabsf(v.w))));
    }
    m = block_reduce_max(m);
    const float sc = fmaxf(__fdiv_rn(m, 32767.0f), 1e-8f);
    for (int i = threadIdx.x * 4; i < DOUT; i += blockDim.x * 4) {
        float4 v = *(const float4*)&p[i];
        v.x = fminf(fmaxf(rintf(__fdiv_rn(v.x, sc)), -32768.0f), 32767.0f) * sc;
        v.y = fminf(fmaxf(rintf(__fdiv_rn(v.y, sc)), -32768.0f), 32767.0f) * sc;
        v.z = fminf(fmaxf(rintf(__fdiv_rn(v.z, sc)), -32768.0f), 32767.0f) * sc;
        v.w = fminf(fmaxf(rintf(__fdiv_rn(v.w, sc)), -32768.0f), 32767.0f) * sc;
        *(float4*)&p[i] = v;
    }
}

// ---------------------------------------------------------------------------
// Launch
// ---------------------------------------------------------------------------
extern "C" void kernel_launch(void* const* d_in, const int* in_sizes, int n_in,
                              void* d_out, int out_size)
{
    const float* d_x = (const float*)d_in[0];
    const float* d_w = (const float*)d_in[1];
    const float* d_b = (const float*)d_in[2];
    const float* d_S = (const float*)d_in[3];
    const float* d_R = (const float*)d_in[4];
    float*       d_o = (float*)d_out;

    float *gW, *gws, *gbias, *gxs, *gxsi;
    __half *gA0, *gA1, *gB0, *gB1;
    int8_t *gQ, *gXh, *gXl;
    cudaGetSymbolAddress((void**)&gW,   g_W);
    cudaGetSymbolAddress((void**)&gQ,   g_Q);
    cudaGetSymbolAddress((void**)&gA0,  g_A0);
    cudaGetSymbolAddress((void**)&gA1,  g_A1);
    cudaGetSymbolAddress((void**)&gB0,  g_B0);
    cudaGetSymbolAddress((void**)&gB1,  g_B1);
    cudaGetSymbolAddress((void**)&gXh,  g_Xh);
    cudaGetSymbolAddress((void**)&gXl,  g_Xl);
    cudaGetSymbolAddress((void**)&gxs,  g_xs);
    cudaGetSymbolAddress((void**)&gxsi, g_xsi);
    cudaGetSymbolAddress((void**)&gws,  g_wscale);
    cudaGetSymbolAddress((void**)&gbias, g_bias);

    cudaFuncSetAttribute(gemm_mma, cudaFuncAttributeMaxDynamicSharedMemorySize, SMEM_DYN);
    cudaFuncSetAttribute(gemm_s8,  cudaFuncAttributeMaxDynamicSharedMemorySize, SMEM_DYN);

    // 1) rotated bias
    rot_bias_kernel<<<DOUT / 256, 256>>>(d_R, d_b, gbias);

    // 2) prep: fp16 splits for GEMM1; int8 split of x for GEMM2
    tsplit2h<<<dim3(DOUT / 32, KR / 32), dim3(32, 8)>>>(d_R, KR, DOUT, nullptr, 64.0f, gA0, gA1);
    tsplit2h<<<dim3(DIN / 32, KR / 32),  dim3(32, 8)>>>(d_w, KR, DIN,  d_S,    64.0f, gB0, gB1);
    xscale_kernel<<<SEQ, 256>>>(d_x, gxs, gxsi);
    xsplit8_kernel<<<(int)((size_t)SEQ * DIN / 4 / 256), 256>>>(d_x, gxsi, gXh, gXl);

    // 3) GEMM1: W' = R^T (weight*S), 3-term fp16 split, alpha = 2^-12 un-scale
    {
        TermsH t;
        t.A[0] = gA0; t.B[0] = gB0;
        t.A[1] = gA0; t.B[1] = gB1;
        t.A[2] = gA1; t.B[2] = gB0;
        dim3 grid(DOUT / 128, DIN / 128);
        gemm_mma<<<grid, 256, SMEM_DYN>>>(t, 3, KR, gW, DIN, 1.0f / 4096.0f);
    }

    // 4) weight quant scale + quantize to int8
    wrowmax_kernel<<<DOUT, 256>>>(gW, gws);
    quant_s8_kernel<<<(int)((size_t)DOUT * DIN / 4 / 256), 256>>>(gW, gws, gQ);

    // 5) GEMM2 (int8, exact): out = (x16 @ q^T) * s_tok*s_o + b'
    {
        dim3 grid(SEQ / 128, DOUT / 128);
        gemm_s8<<<grid, 256, SMEM_DYN>>>(gXh, gXl, gQ, DIN, d_o, DOUT, gxs, gws, gbias);
    }

    // 6) 16-bit per-token fake-quant in place
    out_quant_kernel<<<SEQ, 256>>>(d_o);
}

// round 12
// speedup vs baseline: 1.5154x; 1.0826x over previous
#include <cuda_runtime.h>
#include <cuda_fp16.h>
#include <math.h>
#include <stdint.h>

// Problem dimensions (fixed)
#define SEQ   2048
#define DIN   11008
#define DOUT  4096
#define KR    4096

// ---------------------------------------------------------------------------
// Scratch (__device__ globals; no cudaMalloc allowed)
// ---------------------------------------------------------------------------
__device__ float  g_W [(size_t)DOUT * DIN];   // W' fp32 [o][i]
__device__ int8_t g_Q [(size_t)DOUT * DIN];   // quantized weights int8 [o][i]
__device__ __half g_A0[(size_t)DOUT * KR];    // (R^T * 64) hi  [o][k]
__device__ __half g_A1[(size_t)DOUT * KR];    // lo
__device__ __half g_B0[(size_t)DIN  * KR];    // ((w*S)^T * 64) hi [i][k]
__device__ __half g_B1[(size_t)DIN  * KR];    // lo
__device__ int8_t g_Xh[(size_t)SEQ  * DIN];   // x int16-hi byte [s][i]
__device__ int8_t g_Xl[(size_t)SEQ  * DIN];   // x int16-lo byte [s][i]
__device__ float  g_xs [SEQ];                 // per-token x scale
__device__ float  g_wscale[DOUT];
__device__ float  g_bias  [DOUT];
__device__ float  g_bpart [8 * DOUT];         // rot_bias partials

// ---------------------------------------------------------------------------
// PTX helpers
// ---------------------------------------------------------------------------
__device__ __forceinline__ uint32_t smem_u32(const void* p) {
    return (uint32_t)__cvta_generic_to_shared(p);
}
__device__ __forceinline__ void cp16(uint32_t s, const void* g) {
    asm volatile("cp.async.cg.shared.global [%0], [%1], 16;\n" :: "r"(s), "l"(g));
}
__device__ __forceinline__ void cp_commit() {
    asm volatile("cp.async.commit_group;" ::: "memory");
}
template<int N>
__device__ __forceinline__ void cp_wait() {
    asm volatile("cp.async.wait_group %0;" :: "n"(N) : "memory");
}
__device__ __forceinline__ void ldm4(uint32_t* r, uint32_t addr) {
    asm volatile("ldmatrix.sync.aligned.m8n8.x4.shared.b16 {%0,%1,%2,%3}, [%4];"
        : "=r"(r[0]), "=r"(r[1]), "=r"(r[2]), "=r"(r[3]) : "r"(addr));
}
__device__ __forceinline__ void mma16816(float* d, const uint32_t* a, uint32_t b0, uint32_t b1) {
    asm volatile("mma.sync.aligned.m16n8k16.row.col.f32.f16.f16.f32 "
        "{%0,%1,%2,%3}, {%4,%5,%6,%7}, {%8,%9}, {%0,%1,%2,%3};"
        : "+f"(d[0]), "+f"(d[1]), "+f"(d[2]), "+f"(d[3])
        : "r"(a[0]), "r"(a[1]), "r"(a[2]), "r"(a[3]), "r"(b0), "r"(b1));
}
__device__ __forceinline__ void mma_s8(int* d, const uint32_t* a, uint32_t b0, uint32_t b1) {
    asm volatile("mma.sync.aligned.m16n8k32.row.col.s32.s8.s8.s32 "
        "{%0,%1,%2,%3}, {%4,%5,%6,%7}, {%8,%9}, {%0,%1,%2,%3};"
        : "+r"(d[0]), "+r"(d[1]), "+r"(d[2]), "+r"(d[3])
        : "r"(a[0]), "r"(a[1]), "r"(a[2]), "r"(a[3]), "r"(b0), "r"(b1));
}

// ---------------------------------------------------------------------------
// fp16 GEMM (GEMM1): C = alpha * sum_t A_t @ B_t^T
// Tile 128x128x64, 256 threads (2x4 warps of 64x32), 3-stage cp.async,
// 2 CTAs/SM. 128B rows with full SW128 swizzle: chunk c at row r -> c^(r&7).
// ldmatrix addresses computed inline from row bases (keeps regs < 128).
// ---------------------------------------------------------------------------
struct TermsH { const __half* A[3]; const __half* B[3]; };

#define H_STAGES   3
#define H_STAGE_SZ 32768                       // 16KB A + 16KB B
#define H_SMEM     (H_STAGES * H_STAGE_SZ + 1024)

__global__ __launch_bounds__(256, 2)
void gemm_mma(TermsH t, int nT, int K, float* __restrict__ C, int ldc, float alpha)
{
    extern __shared__ char raw[];
    const uint32_t base = (smem_u32(raw) + 1023u) & ~1023u;

    const int tid  = threadIdx.x;
    const int lane = tid & 31, wid = tid >> 5;
    const int wr   = wid & 1, wc = wid >> 1;
    const int m0   = blockIdx.x * 128, n0 = blockIdx.y * 128;

    // loader: 1024 16B chunks per matrix (128 rows x 8 chunks), 4/thread each
    uint32_t so[4], go[4];
    #pragma unroll
    for (int j = 0; j < 4; j++) {
        int ch = tid + j * 256;
        int r = ch >> 3, c = ch & 7;
        so[j] = (uint32_t)(r * 128 + ((c ^ (r & 7)) << 4));
        go[j] = (uint32_t)(r * K + c * 8);     // halves
    }

    // fragment row bases (bytes); swizzle applied inline per k-step
    const int r7 = lane & 7;
    uint32_t arow[4], brow[2];
    #pragma unroll
    for (int mf = 0; mf < 4; mf++)
        arow[mf] = (uint32_t)((wr * 64 + mf * 16 + (lane & 15)) * 128);
    #pragma unroll
    for (int nf = 0; nf < 2; nf++)
        brow[nf] = (uint32_t)((wc * 32 + nf * 16 + (lane & 7) + ((lane >> 4) << 3)) * 128);
    const int ca = lane >> 4;                  // 0/1 : k16-chunk within 32B pair
    const int cb = (lane >> 3) & 1;

    const int kpt   = K >> 6;                  // 64 halves per stage
    const int total = nT * kpt;
    int lt = 0, lk = 0;
    auto issue = [&](int stage) {
        const __half* ga = t.A[lt] + (size_t)m0 * K + lk * 64;
        const __half* gb = t.B[lt] + (size_t)n0 * K + lk * 64;
        const uint32_t sa = base + stage * H_STAGE_SZ;
        const uint32_t sb = sa + 16384;
        #pragma unroll
        for (int j = 0; j < 4; j++) {
            cp16(sa + so[j], ga + go[j]);
            cp16(sb + so[j], gb + go[j]);
        }
        if (++lk == kpt) { lk = 0; ++lt; }
    };

    float acc[4][4][4];
    #pragma unroll
    for (int i = 0; i < 4; i++)
        #pragma unroll
        for (int j = 0; j < 4; j++)
            #pragma unroll
            for (int k = 0; k < 4; k++) acc[i][j][k] = 0.0f;

    #pragma unroll
    for (int s = 0; s < H_STAGES - 1; s++) {
        if (s < total) issue(s);
        cp_commit();
    }

    int st_c = 0, st_l = H_STAGES - 1;
    for (int i = 0; i < total; i++) {
        cp_wait<H_STAGES - 2>();
        __syncthreads();
        if (i + H_STAGES - 1 < total) issue(st_l);
        cp_commit();
        if (++st_l == H_STAGES) st_l = 0;

        const uint32_t sa = base + st_c * H_STAGE_SZ;
        const uint32_t sb = sa + 16384;
        if (++st_c == H_STAGES) st_c = 0;

        #pragma unroll
        for (int ks = 0; ks < 4; ks++) {
            const int kc = ks * 2;
            uint32_t af[4][4], bf[2][4];
            #pragma unroll
            for (int mf = 0; mf < 4; mf++)
                ldm4(af[mf], sa + arow[mf] + (uint32_t)(((kc + ca) ^ r7) << 4));
            #pragma unroll
            for (int np = 0; np < 2; np++)
                ldm4(bf[np], sb + brow[np] + (uint32_t)(((kc + cb) ^ r7) << 4));
            #pragma unroll
            for (int mf = 0; mf < 4; mf++)
                #pragma unroll
                for (int np = 0; np < 2; np++) {
                    mma16816(acc[mf][np * 2],     af[mf], bf[np][0], bf[np][1]);
                    mma16816(acc[mf][np * 2 + 1], af[mf], bf[np][2], bf[np][3]);
                }
        }
    }

    const int ln4 = lane >> 2, lq = lane & 3;
    #pragma unroll
    for (int mf = 0; mf < 4; mf++) {
        #pragma unroll
        for (int h = 0; h < 2; h++) {
            const int row = m0 + wr * 64 + mf * 16 + ln4 + h * 8;
            float* crow = C + (size_t)row * ldc;
            #pragma unroll
            for (int nf = 0; nf < 4; nf++) {
                const int col = n0 + wc * 32 + nf * 8 + lq * 2;
                *(float2*)&crow[col] = make_float2(acc[mf][nf][h * 2] * alpha,
                                                   acc[mf][nf][h * 2 + 1] * alpha);
            }
        }
    }
}

// ---------------------------------------------------------------------------
// int8 GEMM (GEMM2): out[s][o] = ((256*Xh + Xl) @ Q^T) * rs[s]*cs[o] + cb[o]
// Tile 128x128, BK=64 bytes, 256 threads, 3-stage cp.async, 2 CTAs/SM.
// (unchanged from the passing R11 version)
// ---------------------------------------------------------------------------
#define S_STAGES   3
#define S_STAGE_SZ 16384
#define S_SMEM     (S_STAGES * S_STAGE_SZ + 1024)

__global__ __launch_bounds__(256, 2)
void gemm_s8(const int8_t* __restrict__ Xh, const int8_t* __restrict__ Xl,
             const int8_t* __restrict__ Q, int K,
             float* __restrict__ C, int ldc,
             const float* __restrict__ rs,
             const float* __restrict__ cs, const float* __restrict__ cb)
{
    extern __shared__ char raw[];
    const uint32_t base = (smem_u32(raw) + 1023u) & ~1023u;

    const int tid  = threadIdx.x;
    const int lane = tid & 31, wid = tid >> 5;
    const int wr   = wid & 1, wc = wid >> 1;
    const int m0   = blockIdx.x * 128, n0 = blockIdx.y * 128;

    uint32_t so[2]; uint32_t go[2];
    #pragma unroll
    for (int j = 0; j < 2; j++) {
        int ch = tid + j * 256;
        int r = ch >> 2, c = ch & 3;
        so[j] = (uint32_t)(r * 64 + ((c ^ ((r >> 1) & 3)) << 4));
        go[j] = (uint32_t)(r * K + c * 16);           // bytes
    }

    uint32_t aoff[2][4], boff[2][2];
    #pragma unroll
    for (int ks = 0; ks < 2; ks++) {
        #pragma unroll
        for (int mf = 0; mf < 4; mf++) {
            int r = wr * 64 + mf * 16 + (lane & 15);
            int c = ks * 2 + (lane >> 4);
            aoff[ks][mf] = (uint32_t)(r * 64 + ((c ^ ((r >> 1) & 3)) << 4));
        }
        #pragma unroll
        for (int np = 0; np < 2; np++) {
            int r = wc * 32 + np * 16 + (lane & 15);
            int c = ks * 2 + (lane >> 4);
            boff[ks][np] = (uint32_t)(r * 64 + ((c ^ ((r >> 1) & 3)) << 4));
        }
    }

    const int kpt   = K >> 6;
    const int total = 2 * kpt;
    int lt = 0, lk = 0;
    const int8_t* Aplanes[2] = { Xh, Xl };
    auto issue = [&](int stage) {
        const int8_t* ga = Aplanes[lt] + (size_t)m0 * K + lk * 64;
        const int8_t* gb = Q           + (size_t)n0 * K + lk * 64;
        const uint32_t sa = base + stage * S_STAGE_SZ;
        const uint32_t sb = sa + 8192;
        #pragma unroll
        for (int j = 0; j < 2; j++) {
            cp16(sa + so[j], ga + go[j]);
            cp16(sb + so[j], gb + go[j]);
        }
        if (++lk == kpt) { lk = 0; ++lt; }
    };

    int acc[4][4][4];
    #pragma unroll
    for (int i = 0; i < 4; i++)
        #pragma unroll
        for (int j = 0; j < 4; j++)
            #pragma unroll
            for (int k = 0; k < 4; k++) acc[i][j][k] = 0;

    #pragma unroll
    for (int s = 0; s < S_STAGES - 1; s++) {
        if (s < total) issue(s);
        cp_commit();
    }

    int st_c = 0, st_l = S_STAGES - 1;
    for (int i = 0; i < total; i++) {
        cp_wait<S_STAGES - 2>();
        __syncthreads();
        if (i + S_STAGES - 1 < total) issue(st_l);
        cp_commit();
        if (++st_l == S_STAGES) st_l = 0;

        const uint32_t sa = base + st_c * S_STAGE_SZ;
        const uint32_t sb = sa + 8192;
        if (++st_c == S_STAGES) st_c = 0;

        #pragma unroll
        for (int ks = 0; ks < 2; ks++) {
            uint32_t af[4][4], bf[2][4];
            #pragma unroll
            for (int mf = 0; mf < 4; mf++) ldm4(af[mf], sa + aoff[ks][mf]);
            #pragma unroll
            for (int np = 0; np < 2; np++) ldm4(bf[np], sb + boff[ks][np]);
            #pragma unroll
            for (int mf = 0; mf < 4; mf++)
                #pragma unroll
                for (int np = 0; np < 2; np++) {
                    mma_s8(acc[mf][np * 2],     af[mf], bf[np][0], bf[np][2]);
                    mma_s8(acc[mf][np * 2 + 1], af[mf], bf[np][1], bf[np][3]);
                }
        }

        if (i == kpt - 1) {
            #pragma unroll
            for (int a2 = 0; a2 < 4; a2++)
                #pragma unroll
                for (int b2 = 0; b2 < 4; b2++)
                    #pragma unroll
                    for (int c2 = 0; c2 < 4; c2++) acc[a2][b2][c2] <<= 8;
        }
    }

    const int ln4 = lane >> 2, lq = lane & 3;
    #pragma unroll
    for (int mf = 0; mf < 4; mf++) {
        #pragma unroll
        for (int h = 0; h < 2; h++) {
            const int row = m0 + wr * 64 + mf * 16 + ln4 + h * 8;
            const float srow = __ldg(&rs[row]);
            float* crow = C + (size_t)row * ldc;
            #pragma unroll
            for (int nf = 0; nf < 4; nf++) {
                const int col = n0 + wc * 32 + nf * 8 + lq * 2;
                float v0 = (float)acc[mf][nf][h * 2]     * (srow * __ldg(&cs[col]))     + __ldg(&cb[col]);
                float v1 = (float)acc[mf][nf][h * 2 + 1] * (srow * __ldg(&cs[col + 1])) + __ldg(&cb[col + 1]);
                *(float2*)&crow[col] = make_float2(v0, v1);
            }
        }
    }
}

// ---------------------------------------------------------------------------
// Prep: transpose + pre-scale + 2-way fp16 split (for GEMM1 operands)
// ---------------------------------------------------------------------------
__global__ void tsplit2h(const float* __restrict__ src, int rows, int cols,
                         const float* __restrict__ colScale, float mul,
                         __half* __restrict__ o0, __half* __restrict__ o1)
{
    __shared__ float tsh[32][33];
    const int c0 = blockIdx.x * 32, r0 = blockIdx.y * 32;
    #pragma unroll
    for (int rr = threadIdx.y; rr < 32; rr += 8)
        tsh[rr][threadIdx.x] = src[(size_t)(r0 + rr) * cols + c0 + threadIdx.x];
    __syncthreads();
    #pragma unroll
    for (int cc = threadIdx.y; cc < 32; cc += 8) {
        const int c = c0 + cc;
        float v = tsh[threadIdx.x][cc] * mul;
        if (colScale) v *= colScale[c];
        __half hi = __float2half_rn(v);
        __half lo = __float2half_rn(v - __half2float(hi));
        const size_t off = (size_t)c * rows + r0 + threadIdx.x;
        o0[off] = hi; o1[off] = lo;
    }
}

// ---------------------------------------------------------------------------
// Block reduce (max)
// ---------------------------------------------------------------------------
__device__ __forceinline__ float block_reduce_max(float v) {
    __shared__ float sh[32];
    int lane = threadIdx.x & 31;
    int wid  = threadIdx.x >> 5;
    #pragma unroll
    for (int o = 16; o; o >>= 1) v = fmaxf(v, __shfl_xor_sync(0xffffffffu, v, o));
    if (lane == 0) sh[wid] = v;
    __syncthreads();
    int nw = blockDim.x >> 5;
    v = (threadIdx.x < (unsigned)nw) ? sh[threadIdx.x] : 0.0f;
    if (wid == 0) {
        #pragma unroll
        for (int o = 16; o; o >>= 1) v = fmaxf(v, __shfl_xor_sync(0xffffffffu, v, o));
    }
    if (threadIdx.x == 0) sh[0] = v;
    __syncthreads();
    return sh[0];
}

// ---------------------------------------------------------------------------
// Fused per-token x quant: max -> scale -> int16 -> (hi,lo) int8 planes
// One block per token row; second pass hits L2.
// ---------------------------------------------------------------------------
__global__ void xquant_kernel(const float* __restrict__ x,
                              float* __restrict__ s_out,
                              int8_t* __restrict__ oh, int8_t* __restrict__ ol)
{
    const int row = blockIdx.x;
    const float4* p = (const float4*)(x + (size_t)row * DIN);
    float m = 0.0f;
    for (int i = threadIdx.x; i < DIN / 4; i += blockDim.x) {
        float4 v = p[i];
        m = fmaxf(m, fmaxf(fmaxf(fabsf(v.x), fabsf(v.y)), fmaxf(fabsf(v.z), fabsf(v.w))));
    }
    m = block_reduce_max(m);
    const float sc  = fmaxf(__fdiv_rn(m, 32512.0f), 1e-20f);
    const float inv = __fdiv_rn(1.0f, sc);
    if (threadIdx.x == 0) s_out[row] = sc;

    uint32_t* ph = (uint32_t*)(oh + (size_t)row * DIN);
    uint32_t* pl = (uint32_t*)(ol + (size_t)row * DIN);
    for (int i = threadIdx.x; i < DIN / 4; i += blockDim.x) {
        float4 v = p[i];
        int iv[4];
        iv[0] = (int)fminf(fmaxf(rintf(v.x * inv), -32512.0f), 32512.0f);
        iv[1] = (int)fminf(fmaxf(rintf(v.y * inv), -32512.0f), 32512.0f);
        iv[2] = (int)fminf(fmaxf(rintf(v.z * inv), -32512.0f), 32512.0f);
        iv[3] = (int)fminf(fmaxf(rintf(v.w * inv), -32512.0f), 32512.0f);
        uint32_t hw = 0, lw = 0;
        #pragma unroll
        for (int j = 0; j < 4; j++) {
            int h = (iv[j] + 128) >> 8;
            int l = iv[j] - (h << 8);
            hw |= ((uint32_t)(uint8_t)(int8_t)h) << (j * 8);
            lw |= ((uint32_t)(uint8_t)(int8_t)l) << (j * 8);
        }
        ph[i] = hw;
        pl[i] = lw;
    }
}

// ---------------------------------------------------------------------------
// Fused per-row weight quant: max -> scale -> int8. One block per output row.
// ---------------------------------------------------------------------------
__global__ void wquant_kernel(const float* __restrict__ W,
                              float* __restrict__ scale,
                              int8_t* __restrict__ q)
{
    const int row = blockIdx.x;
    const float4* p = (const float4*)(W + (size_t)row * DIN);
    float m = 0.0f;
    for (int i = threadIdx.x; i < DIN / 4; i += blockDim.x) {
        float4 v = p[i];
        m = fmaxf(m, fmaxf(fmaxf(fabsf(v.x), fabsf(v.y)), fmaxf(fabsf(v.z), fabsf(v.w))));
    }
    m = block_reduce_max(m);
    const float s = fmaxf(__fdiv_rn(m, 127.0f), 1e-8f);
    if (threadIdx.x == 0) scale[row] = s;

    uint32_t* pq = (uint32_t*)(q + (size_t)row * DIN);
    for (int i = threadIdx.x; i < DIN / 4; i += blockDim.x) {
        float4 v = p[i];
        int qx = (int)fminf(fmaxf(rintf(__fdiv_rn(v.x, s)), -128.0f), 127.0f);
        int qy = (int)fminf(fmaxf(rintf(__fdiv_rn(v.y, s)), -128.0f), 127.0f);
        int qz = (int)fminf(fmaxf(rintf(__fdiv_rn(v.z, s)), -128.0f), 127.0f);
        int qw = (int)fminf(fmaxf(rintf(__fdiv_rn(v.w, s)), -128.0f), 127.0f);
        pq[i] = ((uint32_t)(uint8_t)(int8_t)qx)
              | ((uint32_t)(uint8_t)(int8_t)qy << 8)
              | ((uint32_t)(uint8_t)(int8_t)qz << 16)
              | ((uint32_t)(uint8_t)(int8_t)qw << 24);
    }
}

// ---------------------------------------------------------------------------
// Rotated bias, parallel: partials over 8 K-slices, then deterministic reduce
// ---------------------------------------------------------------------------
__global__ void rot_bias_part(const float* __restrict__ R,
                              const float* __restrict__ bias,
                              float* __restrict__ part)
{
    const int o  = blockIdx.x * blockDim.x + threadIdx.x;
    const int k0 = blockIdx.y * (KR / 8);
    float acc = 0.0f;
    for (int k = k0; k < k0 + KR / 8; k++)
        acc = fmaf(R[(size_t)k * DOUT + o], __ldg(&bias[k]), acc);
    part[blockIdx.y * DOUT + o] = acc;
}
__global__ void rot_bias_reduce(const float* __restrict__ part,
                                float* __restrict__ out)
{
    const int o = blockIdx.x * blockDim.x + threadIdx.x;
    float acc = 0.0f;
    #pragma unroll
    for (int j = 0; j < 8; j++) acc += part[j * DOUT + o];
    out[o] = acc;
}

// ---------------------------------------------------------------------------
// 16-bit per-token fake-quant, in place
// ---------------------------------------------------------------------------
__global__ void out_quant_kernel(float* __restrict__ out)
{
    const int s = blockIdx.x;
    float* p = out + (size_t)s * DOUT;
    float m = 0.0f;
    for (int i = threadIdx.x * 4; i < DOUT; i += blockDim.x * 4) {
        float4 v = *(const float4*)&p[i];
        m = fmaxf(m, fmaxf(fmaxf(fabsf(v.x), fabsf(v.y)), fmaxf(fabsf(v.z), fabsf(v.w))));
    }
    m = block_reduce_max(m);
    const float sc = fmaxf(__fdiv_rn(m, 32767.0f), 1e-8f);
    for (int i = threadIdx.x * 4; i < DOUT; i += blockDim.x * 4) {
        float4 v = *(const float4*)&p[i];
        v.x = fminf(fmaxf(rintf(__fdiv_rn(v.x, sc)), -32768.0f), 32767.0f) * sc;
        v.y = fminf(fmaxf(rintf(__fdiv_rn(v.y, sc)), -32768.0f), 32767.0f) * sc;
        v.z = fminf(fmaxf(rintf(__fdiv_rn(v.z, sc)), -32768.0f), 32767.0f) * sc;
        v.w = fminf(fmaxf(rintf(__fdiv_rn(v.w, sc)), -32768.0f), 32767.0f) * sc;
        *(float4*)&p[i] = v;
    }
}

// ---------------------------------------------------------------------------
// Launch
// ---------------------------------------------------------------------------
extern "C" void kernel_launch(void* const* d_in, const int* in_sizes, int n_in,
                              void* d_out, int out_size)
{
    const float* d_x = (const float*)d_in[0];
    const float* d_w = (const float*)d_in[1];
    const float* d_b = (const float*)d_in[2];
    const float* d_S = (const float*)d_in[3];
    const float* d_R = (const float*)d_in[4];
    float*       d_o = (float*)d_out;

    float *gW, *gws, *gbias, *gxs, *gbp;
    __half *gA0, *gA1, *gB0, *gB1;
    int8_t *gQ, *gXh, *gXl;
    cudaGetSymbolAddress((void**)&gW,   g_W);
    cudaGetSymbolAddress((void**)&gQ,   g_Q);
    cudaGetSymbolAddress((void**)&gA0,  g_A0);
    cudaGetSymbolAddress((void**)&gA1,  g_A1);
    cudaGetSymbolAddress((void**)&gB0,  g_B0);
    cudaGetSymbolAddress((void**)&gB1,  g_B1);
    cudaGetSymbolAddress((void**)&gXh,  g_Xh);
    cudaGetSymbolAddress((void**)&gXl,  g_Xl);
    cudaGetSymbolAddress((void**)&gxs,  g_xs);
    cudaGetSymbolAddress((void**)&gws,  g_wscale);
    cudaGetSymbolAddress((void**)&gbias, g_bias);
    cudaGetSymbolAddress((void**)&gbp,  g_bpart);

    cudaFuncSetAttribute(gemm_mma, cudaFuncAttributeMaxDynamicSharedMemorySize, H_SMEM);
    cudaFuncSetAttribute(gemm_s8,  cudaFuncAttributeMaxDynamicSharedMemorySize, S_SMEM);

    // 1) rotated bias (parallel partials + deterministic reduce)
    rot_bias_part<<<dim3(DOUT / 256, 8), 256>>>(d_R, d_b, gbp);
    rot_bias_reduce<<<DOUT / 256, 256>>>(gbp, gbias);

    // 2) prep: fp16 splits for GEMM1; fused per-token x quant for GEMM2
    tsplit2h<<<dim3(DOUT / 32, KR / 32), dim3(32, 8)>>>(d_R, KR, DOUT, nullptr, 64.0f, gA0, gA1);
    tsplit2h<<<dim3(DIN / 32, KR / 32),  dim3(32, 8)>>>(d_w, KR, DIN,  d_S,    64.0f, gB0, gB1);
    xquant_kernel<<<SEQ, 256>>>(d_x, gxs, gXh, gXl);

    // 3) GEMM1: W' = R^T (weight*S), 3-term fp16 split, alpha = 2^-12 un-scale
    {
        TermsH t;
        t.A[0] = gA0; t.B[0] = gB0;
        t.A[1] = gA0; t.B[1] = gB1;
        t.A[2] = gA1; t.B[2] = gB0;
        dim3 grid(DOUT / 128, DIN / 128);
        gemm_mma<<<grid, 256, H_SMEM>>>(t, 3, KR, gW, DIN, 1.0f / 4096.0f);
    }

    // 4) fused weight rowmax + int8 quantize
    wquant_kernel<<<DOUT, 256>>>(gW, gws, gQ);

    // 5) GEMM2 (int8, exact): out = (x16 @ q^T) * s_tok*s_o + b'
    {
        dim3 grid(SEQ / 128, DOUT / 128);
        gemm_s8<<<grid, 256, S_SMEM>>>(gXh, gXl, gQ, DIN, d_o, DOUT, gxs, gws, gbias);
    }

    // 6) 16-bit per-token fake-quant in place
    out_quant_kernel<<<SEQ, 256>>>(d_o);
}

// round 13
// speedup vs baseline: 1.5731x; 1.0380x over previous
#include <cuda_runtime.h>
#include <cuda_fp16.h>
#include <math.h>
#include <stdint.h>

// Problem dimensions (fixed)
#define SEQ   2048
#define DIN   11008
#define DOUT  4096
#define KR    4096

// ---------------------------------------------------------------------------
// Scratch (__device__ globals; no cudaMalloc allowed)
// ---------------------------------------------------------------------------
__device__ float  g_W [(size_t)DOUT * DIN];   // W' fp32 [o][i]
__device__ int8_t g_Q [(size_t)DOUT * DIN];   // quantized weights int8 [o][i]
__device__ __half g_A0[(size_t)DOUT * KR];    // (R^T * 64) hi  [o][k]
__device__ __half g_A1[(size_t)DOUT * KR];    // lo
__device__ __half g_B0[(size_t)DIN  * KR];    // ((w*S)^T * 64) hi [i][k]
__device__ __half g_B1[(size_t)DIN  * KR];    // lo
__device__ int8_t g_Xh[(size_t)SEQ  * DIN];   // x int16-hi byte [s][i]
__device__ int8_t g_Xl[(size_t)SEQ  * DIN];   // x int16-lo byte [s][i]
__device__ float  g_xs [SEQ];                 // per-token x scale
__device__ float  g_wscale[DOUT];
__device__ float  g_bias  [DOUT];
__device__ float  g_bpart [8 * DOUT];         // rot_bias partials

// ---------------------------------------------------------------------------
// PTX helpers
// ---------------------------------------------------------------------------
__device__ __forceinline__ uint32_t smem_u32(const void* p) {
    return (uint32_t)__cvta_generic_to_shared(p);
}
__device__ __forceinline__ void cp16(uint32_t s, const void* g) {
    asm volatile("cp.async.cg.shared.global [%0], [%1], 16;\n" :: "r"(s), "l"(g));
}
__device__ __forceinline__ void cp_commit() {
    asm volatile("cp.async.commit_group;" ::: "memory");
}
template<int N>
__device__ __forceinline__ void cp_wait() {
    asm volatile("cp.async.wait_group %0;" :: "n"(N) : "memory");
}
__device__ __forceinline__ void ldm4(uint32_t* r, uint32_t addr) {
    asm volatile("ldmatrix.sync.aligned.m8n8.x4.shared.b16 {%0,%1,%2,%3}, [%4];"
        : "=r"(r[0]), "=r"(r[1]), "=r"(r[2]), "=r"(r[3]) : "r"(addr));
}
__device__ __forceinline__ void mma16816(float* d, const uint32_t* a, uint32_t b0, uint32_t b1) {
    asm volatile("mma.sync.aligned.m16n8k16.row.col.f32.f16.f16.f32 "
        "{%0,%1,%2,%3}, {%4,%5,%6,%7}, {%8,%9}, {%0,%1,%2,%3};"
        : "+f"(d[0]), "+f"(d[1]), "+f"(d[2]), "+f"(d[3])
        : "r"(a[0]), "r"(a[1]), "r"(a[2]), "r"(a[3]), "r"(b0), "r"(b1));
}
__device__ __forceinline__ void mma_s8(int* d, const uint32_t* a, uint32_t b0, uint32_t b1) {
    asm volatile("mma.sync.aligned.m16n8k32.row.col.s32.s8.s8.s32 "
        "{%0,%1,%2,%3}, {%4,%5,%6,%7}, {%8,%9}, {%0,%1,%2,%3};"
        : "+r"(d[0]), "+r"(d[1]), "+r"(d[2]), "+r"(d[3])
        : "r"(a[0]), "r"(a[1]), "r"(a[2]), "r"(a[3]), "r"(b0), "r"(b1));
}

// ---------------------------------------------------------------------------
// fp16 GEMM (GEMM1): C = alpha * sum_t A_t @ B_t^T   (unchanged from R12)
// Tile 128x128x64, 256 threads (2x4 warps of 64x32), 3-stage cp.async,
// 2 CTAs/SM. 128B rows, full SW128 swizzle: chunk c at row r -> c^(r&7).
// ---------------------------------------------------------------------------
struct TermsH { const __half* A[3]; const __half* B[3]; };

#define H_STAGES   3
#define H_STAGE_SZ 32768
#define H_SMEM     (H_STAGES * H_STAGE_SZ + 1024)

__global__ __launch_bounds__(256, 2)
void gemm_mma(TermsH t, int nT, int K, float* __restrict__ C, int ldc, float alpha)
{
    extern __shared__ char raw[];
    const uint32_t base = (smem_u32(raw) + 1023u) & ~1023u;

    const int tid  = threadIdx.x;
    const int lane = tid & 31, wid = tid >> 5;
    const int wr   = wid & 1, wc = wid >> 1;
    const int m0   = blockIdx.x * 128, n0 = blockIdx.y * 128;

    uint32_t so[4], go[4];
    #pragma unroll
    for (int j = 0; j < 4; j++) {
        int ch = tid + j * 256;
        int r = ch >> 3, c = ch & 7;
        so[j] = (uint32_t)(r * 128 + ((c ^ (r & 7)) << 4));
        go[j] = (uint32_t)(r * K + c * 8);     // halves
    }

    const int r7 = lane & 7;
    uint32_t arow[4], brow[2];
    #pragma unroll
    for (int mf = 0; mf < 4; mf++)
        arow[mf] = (uint32_t)((wr * 64 + mf * 16 + (lane & 15)) * 128);
    #pragma unroll
    for (int nf = 0; nf < 2; nf++)
        brow[nf] = (uint32_t)((wc * 32 + nf * 16 + (lane & 7) + ((lane >> 4) << 3)) * 128);
    const int ca = lane >> 4;
    const int cb = (lane >> 3) & 1;

    const int kpt   = K >> 6;
    const int total = nT * kpt;
    int lt = 0, lk = 0;
    auto issue = [&](int stage) {
        const __half* ga = t.A[lt] + (size_t)m0 * K + lk * 64;
        const __half* gb = t.B[lt] + (size_t)n0 * K + lk * 64;
        const uint32_t sa = base + stage * H_STAGE_SZ;
        const uint32_t sb = sa + 16384;
        #pragma unroll
        for (int j = 0; j < 4; j++) {
            cp16(sa + so[j], ga + go[j]);
            cp16(sb + so[j], gb + go[j]);
        }
        if (++lk == kpt) { lk = 0; ++lt; }
    };

    float acc[4][4][4];
    #pragma unroll
    for (int i = 0; i < 4; i++)
        #pragma unroll
        for (int j = 0; j < 4; j++)
            #pragma unroll
            for (int k = 0; k < 4; k++) acc[i][j][k] = 0.0f;

    #pragma unroll
    for (int s = 0; s < H_STAGES - 1; s++) {
        if (s < total) issue(s);
        cp_commit();
    }

    int st_c = 0, st_l = H_STAGES - 1;
    for (int i = 0; i < total; i++) {
        cp_wait<H_STAGES - 2>();
        __syncthreads();
        if (i + H_STAGES - 1 < total) issue(st_l);
        cp_commit();
        if (++st_l == H_STAGES) st_l = 0;

        const uint32_t sa = base + st_c * H_STAGE_SZ;
        const uint32_t sb = sa + 16384;
        if (++st_c == H_STAGES) st_c = 0;

        #pragma unroll
        for (int ks = 0; ks < 4; ks++) {
            const int kc = ks * 2;
            uint32_t af[4][4], bf[2][4];
            #pragma unroll
            for (int mf = 0; mf < 4; mf++)
                ldm4(af[mf], sa + arow[mf] + (uint32_t)(((kc + ca) ^ r7) << 4));
            #pragma unroll
            for (int np = 0; np < 2; np++)
                ldm4(bf[np], sb + brow[np] + (uint32_t)(((kc + cb) ^ r7) << 4));
            #pragma unroll
            for (int mf = 0; mf < 4; mf++)
                #pragma unroll
                for (int np = 0; np < 2; np++) {
                    mma16816(acc[mf][np * 2],     af[mf], bf[np][0], bf[np][1]);
                    mma16816(acc[mf][np * 2 + 1], af[mf], bf[np][2], bf[np][3]);
                }
        }
    }

    const int ln4 = lane >> 2, lq = lane & 3;
    #pragma unroll
    for (int mf = 0; mf < 4; mf++) {
        #pragma unroll
        for (int h = 0; h < 2; h++) {
            const int row = m0 + wr * 64 + mf * 16 + ln4 + h * 8;
            float* crow = C + (size_t)row * ldc;
            #pragma unroll
            for (int nf = 0; nf < 4; nf++) {
                const int col = n0 + wc * 32 + nf * 8 + lq * 2;
                *(float2*)&crow[col] = make_float2(acc[mf][nf][h * 2] * alpha,
                                                   acc[mf][nf][h * 2 + 1] * alpha);
            }
        }
    }
}

// ---------------------------------------------------------------------------
// int8 GEMM (GEMM2): out[s][o] = ((256*Xh + Xl) @ Q^T) * rs[s]*cs[o] + cb[o]
// Tile 128x128, BK=128 bytes (was 64), 256 threads, 3-stage, 2 CTAs/SM.
// 128B rows, full swizzle c^(r&7); exact s32 acc; <<8 at hi/lo boundary.
// ---------------------------------------------------------------------------
#define S_STAGES   3
#define S_STAGE_SZ 32768
#define S_SMEM     (S_STAGES * S_STAGE_SZ + 1024)

__global__ __launch_bounds__(256, 2)
void gemm_s8(const int8_t* __restrict__ Xh, const int8_t* __restrict__ Xl,
             const int8_t* __restrict__ Q, int K,
             float* __restrict__ C, int ldc,
             const float* __restrict__ rs,
             const float* __restrict__ cs, const float* __restrict__ cb)
{
    extern __shared__ char raw[];
    const uint32_t base = (smem_u32(raw) + 1023u) & ~1023u;

    const int tid  = threadIdx.x;
    const int lane = tid & 31, wid = tid >> 5;
    const int wr   = wid & 1, wc = wid >> 1;
    const int m0   = blockIdx.x * 128, n0 = blockIdx.y * 128;

    // loader: 1024 16B chunks per matrix (128 rows x 8 chunks), 4/thread each
    uint32_t so[4], go[4];
    #pragma unroll
    for (int j = 0; j < 4; j++) {
        int ch = tid + j * 256;
        int r = ch >> 3, c = ch & 7;
        so[j] = (uint32_t)(r * 128 + ((c ^ (r & 7)) << 4));
        go[j] = (uint32_t)(r * K + c * 16);    // bytes
    }

    const int r7 = lane & 7;
    uint32_t arow[4], brow[2];
    #pragma unroll
    for (int mf = 0; mf < 4; mf++)
        arow[mf] = (uint32_t)((wr * 64 + mf * 16 + (lane & 15)) * 128);
    #pragma unroll
    for (int np = 0; np < 2; np++)
        brow[np] = (uint32_t)((wc * 32 + np * 16 + (lane & 15)) * 128);
    const int cx = lane >> 4;                  // 16B chunk selector (A and B)

    const int kpt   = K >> 7;                  // 128 bytes per stage
    const int total = 2 * kpt;                 // hi term then lo term
    int lt = 0, lk = 0;
    const int8_t* Aplanes[2] = { Xh, Xl };
    auto issue = [&](int stage) {
        const int8_t* ga = Aplanes[lt] + (size_t)m0 * K + lk * 128;
        const int8_t* gb = Q           + (size_t)n0 * K + lk * 128;
        const uint32_t sa = base + stage * S_STAGE_SZ;
        const uint32_t sb = sa + 16384;
        #pragma unroll
        for (int j = 0; j < 4; j++) {
            cp16(sa + so[j], ga + go[j]);
            cp16(sb + so[j], gb + go[j]);
        }
        if (++lk == kpt) { lk = 0; ++lt; }
    };

    int acc[4][4][4];
    #pragma unroll
    for (int i = 0; i < 4; i++)
        #pragma unroll
        for (int j = 0; j < 4; j++)
            #pragma unroll
            for (int k = 0; k < 4; k++) acc[i][j][k] = 0;

    #pragma unroll
    for (int s = 0; s < S_STAGES - 1; s++) {
        if (s < total) issue(s);
        cp_commit();
    }

    int st_c = 0, st_l = S_STAGES - 1;
    for (int i = 0; i < total; i++) {
        cp_wait<S_STAGES - 2>();
        __syncthreads();
        if (i + S_STAGES - 1 < total) issue(st_l);
        cp_commit();
        if (++st_l == S_STAGES) st_l = 0;

        const uint32_t sa = base + st_c * S_STAGE_SZ;
        const uint32_t sb = sa + 16384;
        if (++st_c == S_STAGES) st_c = 0;

        #pragma unroll
        for (int ks = 0; ks < 4; ks++) {
            const int kc = ks * 2;
            uint32_t af[4][4], bf[2][4];
            #pragma unroll
            for (int mf = 0; mf < 4; mf++)
                ldm4(af[mf], sa + arow[mf] + (uint32_t)(((kc + cx) ^ r7) << 4));
            #pragma unroll
            for (int np = 0; np < 2; np++)
                ldm4(bf[np], sb + brow[np] + (uint32_t)(((kc + cx) ^ r7) << 4));
            #pragma unroll
            for (int mf = 0; mf < 4; mf++)
                #pragma unroll
                for (int np = 0; np < 2; np++) {
                    mma_s8(acc[mf][np * 2],     af[mf], bf[np][0], bf[np][2]);
                    mma_s8(acc[mf][np * 2 + 1], af[mf], bf[np][1], bf[np][3]);
                }
        }

        if (i == kpt - 1) {                    // hi term done -> scale by 256
            #pragma unroll
            for (int a2 = 0; a2 < 4; a2++)
                #pragma unroll
                for (int b2 = 0; b2 < 4; b2++)
                    #pragma unroll
                    for (int c2 = 0; c2 < 4; c2++) acc[a2][b2][c2] <<= 8;
        }
    }

    const int ln4 = lane >> 2, lq = lane & 3;
    #pragma unroll
    for (int mf = 0; mf < 4; mf++) {
        #pragma unroll
        for (int h = 0; h < 2; h++) {
            const int row = m0 + wr * 64 + mf * 16 + ln4 + h * 8;
            const float srow = __ldg(&rs[row]);
            float* crow = C + (size_t)row * ldc;
            #pragma unroll
            for (int nf = 0; nf < 4; nf++) {
                const int col = n0 + wc * 32 + nf * 8 + lq * 2;
                float v0 = (float)acc[mf][nf][h * 2]     * (srow * __ldg(&cs[col]))     + __ldg(&cb[col]);
                float v1 = (float)acc[mf][nf][h * 2 + 1] * (srow * __ldg(&cs[col + 1])) + __ldg(&cb[col + 1]);
                *(float2*)&crow[col] = make_float2(v0, v1);
            }
        }
    }
}

// ---------------------------------------------------------------------------
// Prep: transpose + pre-scale + 2-way fp16 split, vectorized.
// 32x32 tile, 256 flat threads; float4 loads, uint2 (4-half) stores.
// out[c][r] = split(src[r][c] * mul * colScale[c])
// ---------------------------------------------------------------------------
__global__ void tsplit2h(const float* __restrict__ src, int rows, int cols,
                         const float* __restrict__ colScale, float mul,
                         __half* __restrict__ o0, __half* __restrict__ o1)
{
    __shared__ float tsh[32][33];
    const int tid = threadIdx.x;
    const int c0 = blockIdx.x * 32, r0 = blockIdx.y * 32;

    // load: 1 float4 per thread, store transposed (conflict-free: bank 4c4+r+i)
    {
        const int r = tid >> 3, c4 = tid & 7;
        float4 v = *(const float4*)&src[(size_t)(r0 + r) * cols + c0 + c4 * 4];
        tsh[c4 * 4 + 0][r] = v.x;
        tsh[c4 * 4 + 1][r] = v.y;
        tsh[c4 * 4 + 2][r] = v.z;
        tsh[c4 * 4 + 3][r] = v.w;
    }
    __syncthreads();

    // write: 4 consecutive r per thread, packed as uint2 per plane
    {
        const int c = tid >> 3, r4 = tid & 7;
        const int cg = c0 + c;
        float s = mul;
        if (colScale) s *= colScale[cg];
        uint16_t hu[4], lu[4];
        #pragma unroll
        for (int i = 0; i < 4; i++) {
            float v = tsh[c][r4 * 4 + i] * s;
            __half hi = __float2half_rn(v);
            __half lo = __float2half_rn(v - __half2float(hi));
            hu[i] = *(uint16_t*)&hi;
            lu[i] = *(uint16_t*)&lo;
        }
        const size_t off = (size_t)cg * rows + r0 + r4 * 4;
        *(uint2*)&o0[off] = make_uint2((uint32_t)hu[0] | ((uint32_t)hu[1] << 16),
                                       (uint32_t)hu[2] | ((uint32_t)hu[3] << 16));
        *(uint2*)&o1[off] = make_uint2((uint32_t)lu[0] | ((uint32_t)lu[1] << 16),
                                       (uint32_t)lu[2] | ((uint32_t)lu[3] << 16));
    }
}

// ---------------------------------------------------------------------------
// Block reduce (max)
// ---------------------------------------------------------------------------
__device__ __forceinline__ float block_reduce_max(float v) {
    __shared__ float sh[32];
    int lane = threadIdx.x & 31;
    int wid  = threadIdx.x >> 5;
    #pragma unroll
    for (int o = 16; o; o >>= 1) v = fmaxf(v, __shfl_xor_sync(0xffffffffu, v, o));
    if (lane == 0) sh[wid] = v;
    __syncthreads();
    int nw = blockDim.x >> 5;
    v = (threadIdx.x < (unsigned)nw) ? sh[threadIdx.x] : 0.0f;
    if (wid == 0) {
        #pragma unroll
        for (int o = 16; o; o >>= 1) v = fmaxf(v, __shfl_xor_sync(0xffffffffu, v, o));
    }
    if (threadIdx.x == 0) sh[0] = v;
    __syncthreads();
    return sh[0];
}

// ---------------------------------------------------------------------------
// Fused per-token x quant: max -> scale -> int16 -> (hi,lo) int8 planes
// ---------------------------------------------------------------------------
__global__ void xquant_kernel(const float* __restrict__ x,
                              float* __restrict__ s_out,
                              int8_t* __restrict__ oh, int8_t* __restrict__ ol)
{
    const int row = blockIdx.x;
    const float4* p = (const float4*)(x + (size_t)row * DIN);
    float m = 0.0f;
    for (int i = threadIdx.x; i < DIN / 4; i += blockDim.x) {
        float4 v = p[i];
        m = fmaxf(m, fmaxf(fmaxf(fabsf(v.x), fabsf(v.y)), fmaxf(fabsf(v.z), fabsf(v.w))));
    }
    m = block_reduce_max(m);
    const float sc  = fmaxf(__fdiv_rn(m, 32512.0f), 1e-20f);
    const float inv = __fdiv_rn(1.0f, sc);
    if (threadIdx.x == 0) s_out[row] = sc;

    uint32_t* ph = (uint32_t*)(oh + (size_t)row * DIN);
    uint32_t* pl = (uint32_t*)(ol + (size_t)row * DIN);
    for (int i = threadIdx.x; i < DIN / 4; i += blockDim.x) {
        float4 v = p[i];
        int iv[4];
        iv[0] = (int)fminf(fmaxf(rintf(v.x * inv), -32512.0f), 32512.0f);
        iv[1] = (int)fminf(fmaxf(rintf(v.y * inv), -32512.0f), 32512.0f);
        iv[2] = (int)fminf(fmaxf(rintf(v.z * inv), -32512.0f), 32512.0f);
        iv[3] = (int)fminf(fmaxf(rintf(v.w * inv), -32512.0f), 32512.0f);
        uint32_t hw = 0, lw = 0;
        #pragma unroll
        for (int j = 0; j < 4; j++) {
            int h = (iv[j] + 128) >> 8;
            int l = iv[j] - (h << 8);
            hw |= ((uint32_t)(uint8_t)(int8_t)h) << (j * 8);
            lw |= ((uint32_t)(uint8_t)(int8_t)l) << (j * 8);
        }
        ph[i] = hw;
        pl[i] = lw;
    }
}

// ---------------------------------------------------------------------------
// Fused per-row weight quant: max -> scale -> int8
// ---------------------------------------------------------------------------
__global__ void wquant_kernel(const float* __restrict__ W,
                              float* __restrict__ scale,
                              int8_t* __restrict__ q)
{
    const int row = blockIdx.x;
    const float4* p = (const float4*)(W + (size_t)row * DIN);
    float m = 0.0f;
    for (int i = threadIdx.x; i < DIN / 4; i += blockDim.x) {
        float4 v = p[i];
        m = fmaxf(m, fmaxf(fmaxf(fabsf(v.x), fabsf(v.y)), fmaxf(fabsf(v.z), fabsf(v.w))));
    }
    m = block_reduce_max(m);
    const float s = fmaxf(__fdiv_rn(m, 127.0f), 1e-8f);
    if (threadIdx.x == 0) scale[row] = s;

    uint32_t* pq = (uint32_t*)(q + (size_t)row * DIN);
    for (int i = threadIdx.x; i < DIN / 4; i += blockDim.x) {
        float4 v = p[i];
        int qx = (int)fminf(fmaxf(rintf(__fdiv_rn(v.x, s)), -128.0f), 127.0f);
        int qy = (int)fminf(fmaxf(rintf(__fdiv_rn(v.y, s)), -128.0f), 127.0f);
        int qz = (int)fminf(fmaxf(rintf(__fdiv_rn(v.z, s)), -128.0f), 127.0f);
        int qw = (int)fminf(fmaxf(rintf(__fdiv_rn(v.w, s)), -128.0f), 127.0f);
        pq[i] = ((uint32_t)(uint8_t)(int8_t)qx)
              | ((uint32_t)(uint8_t)(int8_t)qy << 8)
              | ((uint32_t)(uint8_t)(int8_t)qz << 16)
              | ((uint32_t)(uint8_t)(int8_t)qw << 24);
    }
}

// ---------------------------------------------------------------------------
// Rotated bias, parallel: partials over 8 K-slices, then deterministic reduce
// ---------------------------------------------------------------------------
__global__ void rot_bias_part(const float* __restrict__ R,
                              const float* __restrict__ bias,
                              float* __restrict__ part)
{
    const int o  = blockIdx.x * blockDim.x + threadIdx.x;
    const int k0 = blockIdx.y * (KR / 8);
    float acc = 0.0f;
    for (int k = k0; k < k0 + KR / 8; k++)
        acc = fmaf(R[(size_t)k * DOUT + o], __ldg(&bias[k]), acc);
    part[blockIdx.y * DOUT + o] = acc;
}
__global__ void rot_bias_reduce(const float* __restrict__ part,
                                float* __restrict__ out)
{
    const int o = blockIdx.x * blockDim.x + threadIdx.x;
    float acc = 0.0f;
    #pragma unroll
    for (int j = 0; j < 8; j++) acc += part[j * DOUT + o];
    out[o] = acc;
}

// ---------------------------------------------------------------------------
// 16-bit per-token fake-quant, in place
// ---------------------------------------------------------------------------
__global__ void out_quant_kernel(float* __restrict__ out)
{
    const int s = blockIdx.x;
    float* p = out + (size_t)s * DOUT;
    float m = 0.0f;
    for (int i = threadIdx.x * 4; i < DOUT; i += blockDim.x * 4) {
        float4 v = *(const float4*)&p[i];
        m = fmaxf(m, fmaxf(fmaxf(fabsf(v.x), fabsf(v.y)), fmaxf(fabsf(v.z), fabsf(v.w))));
    }
    m = block_reduce_max(m);
    const float sc = fmaxf(__fdiv_rn(m, 32767.0f), 1e-8f);
    for (int i = threadIdx.x * 4; i < DOUT; i += blockDim.x * 4) {
        float4 v = *(const float4*)&p[i];
        v.x = fminf(fmaxf(rintf(__fdiv_rn(v.x, sc)), -32768.0f), 32767.0f) * sc;
        v.y = fminf(fmaxf(rintf(__fdiv_rn(v.y, sc)), -32768.0f), 32767.0f) * sc;
        v.z = fminf(fmaxf(rintf(__fdiv_rn(v.z, sc)), -32768.0f), 32767.0f) * sc;
        v.w = fminf(fmaxf(rintf(__fdiv_rn(v.w, sc)), -32768.0f), 32767.0f) * sc;
        *(float4*)&p[i] = v;
    }
}

// ---------------------------------------------------------------------------
// Launch
// ---------------------------------------------------------------------------
extern "C" void kernel_launch(void* const* d_in, const int* in_sizes, int n_in,
                              void* d_out, int out_size)
{
    const float* d_x = (const float*)d_in[0];
    const float* d_w = (const float*)d_in[1];
    const float* d_b = (const float*)d_in[2];
    const float* d_S = (const float*)d_in[3];
    const float* d_R = (const float*)d_in[4];
    float*       d_o = (float*)d_out;

    float *gW, *gws, *gbias, *gxs, *gbp;
    __half *gA0, *gA1, *gB0, *gB1;
    int8_t *gQ, *gXh, *gXl;
    cudaGetSymbolAddress((void**)&gW,   g_W);
    cudaGetSymbolAddress((void**)&gQ,   g_Q);
    cudaGetSymbolAddress((void**)&gA0,  g_A0);
    cudaGetSymbolAddress((void**)&gA1,  g_A1);
    cudaGetSymbolAddress((void**)&gB0,  g_B0);
    cudaGetSymbolAddress((void**)&gB1,  g_B1);
    cudaGetSymbolAddress((void**)&gXh,  g_Xh);
    cudaGetSymbolAddress((void**)&gXl,  g_Xl);
    cudaGetSymbolAddress((void**)&gxs,  g_xs);
    cudaGetSymbolAddress((void**)&gws,  g_wscale);
    cudaGetSymbolAddress((void**)&gbias, g_bias);
    cudaGetSymbolAddress((void**)&gbp,  g_bpart);

    cudaFuncSetAttribute(gemm_mma, cudaFuncAttributeMaxDynamicSharedMemorySize, H_SMEM);
    cudaFuncSetAttribute(gemm_s8,  cudaFuncAttributeMaxDynamicSharedMemorySize, S_SMEM);

    // 1) rotated bias (parallel partials + deterministic reduce)
    rot_bias_part<<<dim3(DOUT / 256, 8), 256>>>(d_R, d_b, gbp);
    rot_bias_reduce<<<DOUT / 256, 256>>>(gbp, gbias);

    // 2) prep: fp16 splits for GEMM1; fused per-token x quant for GEMM2
    tsplit2h<<<dim3(DOUT / 32, KR / 32), 256>>>(d_R, KR, DOUT, nullptr, 64.0f, gA0, gA1);
    tsplit2h<<<dim3(DIN / 32, KR / 32),  256>>>(d_w, KR, DIN,  d_S,    64.0f, gB0, gB1);
    xquant_kernel<<<SEQ, 256>>>(d_x, gxs, gXh, gXl);

    // 3) GEMM1: W' = R^T (weight*S), 3-term fp16 split, alpha = 2^-12 un-scale
    {
        TermsH t;
        t.A[0] = gA0; t.B[0] = gB0;
        t.A[1] = gA0; t.B[1] = gB1;
        t.A[2] = gA1; t.B[2] = gB0;
        dim3 grid(DOUT / 128, DIN / 128);
        gemm_mma<<<grid, 256, H_SMEM>>>(t, 3, KR, gW, DIN, 1.0f / 4096.0f);
    }

    // 4) fused weight rowmax + int8 quantize
    wquant_kernel<<<DOUT, 256>>>(gW, gws, gQ);

    // 5) GEMM2 (int8, exact): out = (x16 @ q^T) * s_tok*s_o + b'
    {
        dim3 grid(SEQ / 128, DOUT / 128);
        gemm_s8<<<grid, 256, S_SMEM>>>(gXh, gXl, gQ, DIN, d_o, DOUT, gxs, gws, gbias);
    }

    // 6) 16-bit per-token fake-quant in place
    out_quant_kernel<<<SEQ, 256>>>(d_o);
}

// round 16
// speedup vs baseline: 1.6369x; 1.0406x over previous
#include <cuda_runtime.h>
#include <cuda_fp16.h>
#include <math.h>
#include <stdint.h>

// Problem dimensions (fixed)
#define SEQ   2048
#define DIN   11008
#define DOUT  4096
#define KR    4096

// ---------------------------------------------------------------------------
// Scratch (__device__ globals; no cudaMalloc allowed)
// ---------------------------------------------------------------------------
__device__ float  g_W [(size_t)DOUT * DIN];   // W' fp32 [o][i]
__device__ int8_t g_Q [(size_t)DOUT * DIN];   // quantized weights int8 [o][i]
__device__ __half g_A0[(size_t)DOUT * KR];    // (R^T * 64) hi  [o][k]
__device__ __half g_A1[(size_t)DOUT * KR];    // lo
__device__ __half g_B0[(size_t)DIN  * KR];    // ((w*S)^T * 64) hi [i][k]
__device__ __half g_B1[(size_t)DIN  * KR];    // lo
__device__ int8_t g_Xh[(size_t)SEQ  * DIN];   // x int16-hi byte [s][i]
__device__ int8_t g_Xl[(size_t)SEQ  * DIN];   // x int16-lo byte [s][i]
__device__ float  g_xs [SEQ];                 // per-token x scale
__device__ float  g_wscale[DOUT];
__device__ float  g_bias  [DOUT];
__device__ float  g_bpart [8 * DOUT];         // rot_bias partials

// ---------------------------------------------------------------------------
// PTX helpers
// ---------------------------------------------------------------------------
__device__ __forceinline__ uint32_t smem_u32(const void* p) {
    return (uint32_t)__cvta_generic_to_shared(p);
}
__device__ __forceinline__ void cp16(uint32_t s, const void* g) {
    asm volatile("cp.async.cg.shared.global [%0], [%1], 16;\n" :: "r"(s), "l"(g));
}
__device__ __forceinline__ void cp_commit() {
    asm volatile("cp.async.commit_group;" ::: "memory");
}
template<int N>
__device__ __forceinline__ void cp_wait() {
    asm volatile("cp.async.wait_group %0;" :: "n"(N) : "memory");
}
__device__ __forceinline__ void ldm4(uint32_t* r, uint32_t addr) {
    asm volatile("ldmatrix.sync.aligned.m8n8.x4.shared.b16 {%0,%1,%2,%3}, [%4];"
        : "=r"(r[0]), "=r"(r[1]), "=r"(r[2]), "=r"(r[3]) : "r"(addr));
}
__device__ __forceinline__ void mma16816(float* d, const uint32_t* a, uint32_t b0, uint32_t b1) {
    asm volatile("mma.sync.aligned.m16n8k16.row.col.f32.f16.f16.f32 "
        "{%0,%1,%2,%3}, {%4,%5,%6,%7}, {%8,%9}, {%0,%1,%2,%3};"
        : "+f"(d[0]), "+f"(d[1]), "+f"(d[2]), "+f"(d[3])
        : "r"(a[0]), "r"(a[1]), "r"(a[2]), "r"(a[3]), "r"(b0), "r"(b1));
}
__device__ __forceinline__ void mma_s8(int* d, const uint32_t* a, uint32_t b0, uint32_t b1) {
    asm volatile("mma.sync.aligned.m16n8k32.row.col.s32.s8.s8.s32 "
        "{%0,%1,%2,%3}, {%4,%5,%6,%7}, {%8,%9}, {%0,%1,%2,%3};"
        : "+r"(d[0]), "+r"(d[1]), "+r"(d[2]), "+r"(d[3])
        : "r"(a[0]), "r"(a[1]), "r"(a[2]), "r"(a[3]), "r"(b0), "r"(b1));
}

// ---------------------------------------------------------------------------
// Fused GEMM1: C = alpha * (A0@B0^T + A0@B1^T + A1@B0^T), one K-pass.
// Tile 128x128x32, 256 threads (2x4 warps of 64x32), 3-stage cp.async,
// 2 CTAs/SM. 64B smem rows, swizzle: chunk c at row r -> c ^ ((r>>1)&3).
// Per ks: frags(A0,B0,B1) -> A0*B0, A0*B1; reload frags <- A1 -> A1*B0.
// ---------------------------------------------------------------------------
#define H_STAGES   3
#define H_STAGE_SZ 32768                       // A0|A1|B0|B1 x 8KB
#define H_SMEM     (H_STAGES * H_STAGE_SZ + 1024)

__global__ __launch_bounds__(256, 2)
void gemm1_fused(const __half* __restrict__ A0, const __half* __restrict__ A1,
                 const __half* __restrict__ B0, const __half* __restrict__ B1,
                 int K, float* __restrict__ C, int ldc, float alpha)
{
    extern __shared__ char raw[];
    const uint32_t base = (smem_u32(raw) + 1023u) & ~1023u;

    const int tid  = threadIdx.x;
    const int lane = tid & 31, wid = tid >> 5;
    const int wr   = wid & 1, wc = wid >> 1;
    const int m0   = blockIdx.x * 128, n0 = blockIdx.y * 128;

    // loader: per matrix 512 16B chunks (128 rows x 4), 2/thread
    uint32_t so[2], go[2];
    #pragma unroll
    for (int j = 0; j < 2; j++) {
        int ch = tid + j * 256;
        int r = ch >> 2, c = ch & 3;
        so[j] = (uint32_t)(r * 64 + ((c ^ ((r >> 1) & 3)) << 4));
        go[j] = (uint32_t)(r * K + c * 8);     // halves
    }

    // ldmatrix per-lane byte offsets (proven R5-R11 pattern, BK=32)
    uint32_t aoff[2][4], boff[2][2];
    #pragma unroll
    for (int ks = 0; ks < 2; ks++) {
        #pragma unroll
        for (int mf = 0; mf < 4; mf++) {
            int r = wr * 64 + mf * 16 + (lane & 15);
            int c = ks * 2 + (lane >> 4);
            aoff[ks][mf] = (uint32_t)(r * 64 + ((c ^ ((r >> 1) & 3)) << 4));
        }
        #pragma unroll
        for (int nf = 0; nf < 2; nf++) {
            int r = wc * 32 + nf * 16 + (lane & 7) + ((lane >> 4) << 3);
            int c = ks * 2 + ((lane >> 3) & 1);
            boff[ks][nf] = (uint32_t)(r * 64 + ((c ^ ((r >> 1) & 3)) << 4));
        }
    }

    const int total = K >> 5;                  // one pass over K, all terms
    int lk = 0;
    auto issue = [&](int stage) {
        const __half* ga0 = A0 + (size_t)m0 * K + lk * 32;
        const __half* ga1 = A1 + (size_t)m0 * K + lk * 32;
        const __half* gb0 = B0 + (size_t)n0 * K + lk * 32;
        const __half* gb1 = B1 + (size_t)n0 * K + lk * 32;
        const uint32_t s0 = base + stage * H_STAGE_SZ;
        #pragma unroll
        for (int j = 0; j < 2; j++) {
            cp16(s0         + so[j], ga0 + go[j]);
            cp16(s0 +  8192 + so[j], ga1 + go[j]);
            cp16(s0 + 16384 + so[j], gb0 + go[j]);
            cp16(s0 + 24576 + so[j], gb1 + go[j]);
        }
        ++lk;
    };

    float acc[4][4][4];
    #pragma unroll
    for (int i = 0; i < 4; i++)
        #pragma unroll
        for (int j = 0; j < 4; j++)
            #pragma unroll
            for (int k = 0; k < 4; k++) acc[i][j][k] = 0.0f;

    #pragma unroll
    for (int s = 0; s < H_STAGES - 1; s++) {
        if (s < total) issue(s);
        cp_commit();
    }

    int st_c = 0, st_l = H_STAGES - 1;
    for (int i = 0; i < total; i++) {
        cp_wait<H_STAGES - 2>();
        __syncthreads();
        if (i + H_STAGES - 1 < total) issue(st_l);
        cp_commit();
        if (++st_l == H_STAGES) st_l = 0;

        const uint32_t s0 = base + st_c * H_STAGE_SZ;
        if (++st_c == H_STAGES) st_c = 0;

        #pragma unroll
        for (int ks = 0; ks < 2; ks++) {
            uint32_t af[4][4], b0f[2][4], b1f[2][4];
            #pragma unroll
            for (int mf = 0; mf < 4; mf++) ldm4(af[mf], s0 + aoff[ks][mf]);
            #pragma unroll
            for (int np = 0; np < 2; np++) {
                ldm4(b0f[np], s0 + 16384 + boff[ks][np]);
                ldm4(b1f[np], s0 + 24576 + boff[ks][np]);
            }
            // A0*B0 and A0*B1
            #pragma unroll
            for (int mf = 0; mf < 4; mf++)
                #pragma unroll
                for (int np = 0; np < 2; np++) {
                    mma16816(acc[mf][np * 2],     af[mf], b0f[np][0], b0f[np][1]);
                    mma16816(acc[mf][np * 2 + 1], af[mf], b0f[np][2], b0f[np][3]);
                    mma16816(acc[mf][np * 2],     af[mf], b1f[np][0], b1f[np][1]);
                    mma16816(acc[mf][np * 2 + 1], af[mf], b1f[np][2], b1f[np][3]);
                }
            // reload frags <- A1, then A1*B0
            #pragma unroll
            for (int mf = 0; mf < 4; mf++) ldm4(af[mf], s0 + 8192 + aoff[ks][mf]);
            #pragma unroll
            for (int mf = 0; mf < 4; mf++)
                #pragma unroll
                for (int np = 0; np < 2; np++) {
                    mma16816(acc[mf][np * 2],     af[mf], b0f[np][0], b0f[np][1]);
                    mma16816(acc[mf][np * 2 + 1], af[mf], b0f[np][2], b0f[np][3]);
                }
        }
    }

    const int ln4 = lane >> 2, lq = lane & 3;
    #pragma unroll
    for (int mf = 0; mf < 4; mf++) {
        #pragma unroll
        for (int h = 0; h < 2; h++) {
            const int row = m0 + wr * 64 + mf * 16 + ln4 + h * 8;
            float* crow = C + (size_t)row * ldc;
            #pragma unroll
            for (int nf = 0; nf < 4; nf++) {
                const int col = n0 + wc * 32 + nf * 8 + lq * 2;
                *(float2*)&crow[col] = make_float2(acc[mf][nf][h * 2] * alpha,
                                                   acc[mf][nf][h * 2 + 1] * alpha);
            }
        }
    }
}

// ---------------------------------------------------------------------------
// int8 GEMM (GEMM2): out[s][o] = ((256*Xh + Xl) @ Q^T) * rs[s]*cs[o] + cb[o]
// Tile 128x128, BK=128 bytes, 256 threads, 3-stage, 2 CTAs/SM (R13-proven).
// ---------------------------------------------------------------------------
#define S_STAGES   3
#define S_STAGE_SZ 32768
#define S_SMEM     (S_STAGES * S_STAGE_SZ + 1024)

__global__ __launch_bounds__(256, 2)
void gemm_s8(const int8_t* __restrict__ Xh, const int8_t* __restrict__ Xl,
             const int8_t* __restrict__ Q, int K,
             float* __restrict__ C, int ldc,
             const float* __restrict__ rs,
             const float* __restrict__ cs, const float* __restrict__ cb)
{
    extern __shared__ char raw[];
    const uint32_t base = (smem_u32(raw) + 1023u) & ~1023u;

    const int tid  = threadIdx.x;
    const int lane = tid & 31, wid = tid >> 5;
    const int wr   = wid & 1, wc = wid >> 1;
    const int m0   = blockIdx.x * 128, n0 = blockIdx.y * 128;

    uint32_t so[4], go[4];
    #pragma unroll
    for (int j = 0; j < 4; j++) {
        int ch = tid + j * 256;
        int r = ch >> 3, c = ch & 7;
        so[j] = (uint32_t)(r * 128 + ((c ^ (r & 7)) << 4));
        go[j] = (uint32_t)(r * K + c * 16);    // bytes
    }

    const int r7 = lane & 7;
    uint32_t arow[4], brow[2];
    #pragma unroll
    for (int mf = 0; mf < 4; mf++)
        arow[mf] = (uint32_t)((wr * 64 + mf * 16 + (lane & 15)) * 128);
    #pragma unroll
    for (int np = 0; np < 2; np++)
        brow[np] = (uint32_t)((wc * 32 + np * 16 + (lane & 15)) * 128);
    const int cx = lane >> 4;

    const int kpt   = K >> 7;
    const int total = 2 * kpt;
    int lt = 0, lk = 0;
    const int8_t* Aplanes[2] = { Xh, Xl };
    auto issue = [&](int stage) {
        const int8_t* ga = Aplanes[lt] + (size_t)m0 * K + lk * 128;
        const int8_t* gb = Q           + (size_t)n0 * K + lk * 128;
        const uint32_t sa = base + stage * S_STAGE_SZ;
        const uint32_t sb = sa + 16384;
        #pragma unroll
        for (int j = 0; j < 4; j++) {
            cp16(sa + so[j], ga + go[j]);
            cp16(sb + so[j], gb + go[j]);
        }
        if (++lk == kpt) { lk = 0; ++lt; }
    };

    int acc[4][4][4];
    #pragma unroll
    for (int i = 0; i < 4; i++)
        #pragma unroll
        for (int j = 0; j < 4; j++)
            #pragma unroll
            for (int k = 0; k < 4; k++) acc[i][j][k] = 0;

    #pragma unroll
    for (int s = 0; s < S_STAGES - 1; s++) {
        if (s < total) issue(s);
        cp_commit();
    }

    int st_c = 0, st_l = S_STAGES - 1;
    for (int i = 0; i < total; i++) {
        cp_wait<S_STAGES - 2>();
        __syncthreads();
        if (i + S_STAGES - 1 < total) issue(st_l);
        cp_commit();
        if (++st_l == S_STAGES) st_l = 0;

        const uint32_t sa = base + st_c * S_STAGE_SZ;
        const uint32_t sb = sa + 16384;
        if (++st_c == S_STAGES) st_c = 0;

        #pragma unroll
        for (int ks = 0; ks < 4; ks++) {
            const int kc = ks * 2;
            uint32_t af[4][4], bf[2][4];
            #pragma unroll
            for (int mf = 0; mf < 4; mf++)
                ldm4(af[mf], sa + arow[mf] + (uint32_t)(((kc + cx) ^ r7) << 4));
            #pragma unroll
            for (int np = 0; np < 2; np++)
                ldm4(bf[np], sb + brow[np] + (uint32_t)(((kc + cx) ^ r7) << 4));
            #pragma unroll
            for (int mf = 0; mf < 4; mf++)
                #pragma unroll
                for (int np = 0; np < 2; np++) {
                    mma_s8(acc[mf][np * 2],     af[mf], bf[np][0], bf[np][2]);
                    mma_s8(acc[mf][np * 2 + 1], af[mf], bf[np][1], bf[np][3]);
                }
        }

        if (i == kpt - 1) {
            #pragma unroll
            for (int a2 = 0; a2 < 4; a2++)
                #pragma unroll
                for (int b2 = 0; b2 < 4; b2++)
                    #pragma unroll
                    for (int c2 = 0; c2 < 4; c2++) acc[a2][b2][c2] <<= 8;
        }
    }

    const int ln4 = lane >> 2, lq = lane & 3;
    #pragma unroll
    for (int mf = 0; mf < 4; mf++) {
        #pragma unroll
        for (int h = 0; h < 2; h++) {
            const int row = m0 + wr * 64 + mf * 16 + ln4 + h * 8;
            const float srow = __ldg(&rs[row]);
            float* crow = C + (size_t)row * ldc;
            #pragma unroll
            for (int nf = 0; nf < 4; nf++) {
                const int col = n0 + wc * 32 + nf * 8 + lq * 2;
                float v0 = (float)acc[mf][nf][h * 2]     * (srow * __ldg(&cs[col]))     + __ldg(&cb[col]);
                float v1 = (float)acc[mf][nf][h * 2 + 1] * (srow * __ldg(&cs[col + 1])) + __ldg(&cb[col + 1]);
                *(float2*)&crow[col] = make_float2(v0, v1);
            }
        }
    }
}

// ---------------------------------------------------------------------------
// Prep: transpose + pre-scale + 2-way fp16 split, vectorized (R13-proven)
// ---------------------------------------------------------------------------
__global__ void tsplit2h(const float* __restrict__ src, int rows, int cols,
                         const float* __restrict__ colScale, float mul,
                         __half* __restrict__ o0, __half* __restrict__ o1)
{
    __shared__ float tsh[32][33];
    const int tid = threadIdx.x;
    const int c0 = blockIdx.x * 32, r0 = blockIdx.y * 32;

    {
        const int r = tid >> 3, c4 = tid & 7;
        float4 v = *(const float4*)&src[(size_t)(r0 + r) * cols + c0 + c4 * 4];
        tsh[c4 * 4 + 0][r] = v.x;
        tsh[c4 * 4 + 1][r] = v.y;
        tsh[c4 * 4 + 2][r] = v.z;
        tsh[c4 * 4 + 3][r] = v.w;
    }
    __syncthreads();

    {
        const int c = tid >> 3, r4 = tid & 7;
        const int cg = c0 + c;
        float s = mul;
        if (colScale) s *= colScale[cg];
        uint16_t hu[4], lu[4];
        #pragma unroll
        for (int i = 0; i < 4; i++) {
            float v = tsh[c][r4 * 4 + i] * s;
            __half hi = __float2half_rn(v);
            __half lo = __float2half_rn(v - __half2float(hi));
            hu[i] = *(uint16_t*)&hi;
            lu[i] = *(uint16_t*)&lo;
        }
        const size_t off = (size_t)cg * rows + r0 + r4 * 4;
        *(uint2*)&o0[off] = make_uint2((uint32_t)hu[0] | ((uint32_t)hu[1] << 16),
                                       (uint32_t)hu[2] | ((uint32_t)hu[3] << 16));
        *(uint2*)&o1[off] = make_uint2((uint32_t)lu[0] | ((uint32_t)lu[1] << 16),
                                       (uint32_t)lu[2] | ((uint32_t)lu[3] << 16));
    }
}

// ---------------------------------------------------------------------------
// Block reduce (max)
// ---------------------------------------------------------------------------
__device__ __forceinline__ float block_reduce_max(float v) {
    __shared__ float sh[32];
    int lane = threadIdx.x & 31;
    int wid  = threadIdx.x >> 5;
    #pragma unroll
    for (int o = 16; o; o >>= 1) v = fmaxf(v, __shfl_xor_sync(0xffffffffu, v, o));
    if (lane == 0) sh[wid] = v;
    __syncthreads();
    int nw = blockDim.x >> 5;
    v = (threadIdx.x < (unsigned)nw) ? sh[threadIdx.x] : 0.0f;
    if (wid == 0) {
        #pragma unroll
        for (int o = 16; o; o >>= 1) v = fmaxf(v, __shfl_xor_sync(0xffffffffu, v, o));
    }
    if (threadIdx.x == 0) sh[0] = v;
    __syncthreads();
    return sh[0];
}

// ---------------------------------------------------------------------------
// Fused per-token x quant: max -> scale -> int16 -> (hi,lo) int8 planes
// ---------------------------------------------------------------------------
__global__ void xquant_kernel(const float* __restrict__ x,
                              float* __restrict__ s_out,
                              int8_t* __restrict__ oh, int8_t* __restrict__ ol)
{
    const int row = blockIdx.x;
    const float4* p = (const float4*)(x + (size_t)row * DIN);
    float m = 0.0f;
    for (int i = threadIdx.x; i < DIN / 4; i += blockDim.x) {
        float4 v = p[i];
        m = fmaxf(m, fmaxf(fmaxf(fabsf(v.x), fabsf(v.y)), fmaxf(fabsf(v.z), fabsf(v.w))));
    }
    m = block_reduce_max(m);
    const float sc  = fmaxf(__fdiv_rn(m, 32512.0f), 1e-20f);
    const float inv = __fdiv_rn(1.0f, sc);
    if (threadIdx.x == 0) s_out[row] = sc;

    uint32_t* ph = (uint32_t*)(oh + (size_t)row * DIN);
    uint32_t* pl = (uint32_t*)(ol + (size_t)row * DIN);
    for (int i = threadIdx.x; i < DIN / 4; i += blockDim.x) {
        float4 v = p[i];
        int iv[4];
        iv[0] = (int)fminf(fmaxf(rintf(v.x * inv), -32512.0f), 32512.0f);
        iv[1] = (int)fminf(fmaxf(rintf(v.y * inv), -32512.0f), 32512.0f);
        iv[2] = (int)fminf(fmaxf(rintf(v.z * inv), -32512.0f), 32512.0f);
        iv[3] = (int)fminf(fmaxf(rintf(v.w * inv), -32512.0f), 32512.0f);
        uint32_t hw = 0, lw = 0;
        #pragma unroll
        for (int j = 0; j < 4; j++) {
            int h = (iv[j] + 128) >> 8;
            int l = iv[j] - (h << 8);
            hw |= ((uint32_t)(uint8_t)(int8_t)h) << (j * 8);
            lw |= ((uint32_t)(uint8_t)(int8_t)l) << (j * 8);
        }
        ph[i] = hw;
        pl[i] = lw;
    }
}

// ---------------------------------------------------------------------------
// Fused per-row weight quant: max -> scale -> int8
// ---------------------------------------------------------------------------
__global__ void wquant_kernel(const float* __restrict__ W,
                              float* __restrict__ scale,
                              int8_t* __restrict__ q)
{
    const int row = blockIdx.x;
    const float4* p = (const float4*)(W + (size_t)row * DIN);
    float m = 0.0f;
    for (int i = threadIdx.x; i < DIN / 4; i += blockDim.x) {
        float4 v = p[i];
        m = fmaxf(m, fmaxf(fmaxf(fabsf(v.x), fabsf(v.y)), fmaxf(fabsf(v.z), fabsf(v.w))));
    }
    m = block_reduce_max(m);
    const float s = fmaxf(__fdiv_rn(m, 127.0f), 1e-8f);
    if (threadIdx.x == 0) scale[row] = s;

    uint32_t* pq = (uint32_t*)(q + (size_t)row * DIN);
    for (int i = threadIdx.x; i < DIN / 4; i += blockDim.x) {
        float4 v = p[i];
        int qx = (int)fminf(fmaxf(rintf(__fdiv_rn(v.x, s)), -128.0f), 127.0f);
        int qy = (int)fminf(fmaxf(rintf(__fdiv_rn(v.y, s)), -128.0f), 127.0f);
        int qz = (int)fminf(fmaxf(rintf(__fdiv_rn(v.z, s)), -128.0f), 127.0f);
        int qw = (int)fminf(fmaxf(rintf(__fdiv_rn(v.w, s)), -128.0f), 127.0f);
        pq[i] = ((uint32_t)(uint8_t)(int8_t)qx)
              | ((uint32_t)(uint8_t)(int8_t)qy << 8)
              | ((uint32_t)(uint8_t)(int8_t)qz << 16)
              | ((uint32_t)(uint8_t)(int8_t)qw << 24);
    }
}

// ---------------------------------------------------------------------------
// Rotated bias, parallel: partials over 8 K-slices, then deterministic reduce
// ---------------------------------------------------------------------------
__global__ void rot_bias_part(const float* __restrict__ R,
                              const float* __restrict__ bias,
                              float* __restrict__ part)
{
    const int o  = blockIdx.x * blockDim.x + threadIdx.x;
    const int k0 = blockIdx.y * (KR / 8);
    float acc = 0.0f;
    for (int k = k0; k < k0 + KR / 8; k++)
        acc = fmaf(R[(size_t)k * DOUT + o], __ldg(&bias[k]), acc);
    part[blockIdx.y * DOUT + o] = acc;
}
__global__ void rot_bias_reduce(const float* __restrict__ part,
                                float* __restrict__ out)
{
    const int o = blockIdx.x * blockDim.x + threadIdx.x;
    float acc = 0.0f;
    #pragma unroll
    for (int j = 0; j < 8; j++) acc += part[j * DOUT + o];
    out[o] = acc;
}

// ---------------------------------------------------------------------------
// 16-bit per-token fake-quant, in place
// ---------------------------------------------------------------------------
__global__ void out_quant_kernel(float* __restrict__ out)
{
    const int s = blockIdx.x;
    float* p = out + (size_t)s * DOUT;
    float m = 0.0f;
    for (int i = threadIdx.x * 4; i < DOUT; i += blockDim.x * 4) {
        float4 v = *(const float4*)&p[i];
        m = fmaxf(m, fmaxf(fmaxf(fabsf(v.x), fabsf(v.y)), fmaxf(fabsf(v.z), fabsf(v.w))));
    }
    m = block_reduce_max(m);
    const float sc = fmaxf(__fdiv_rn(m, 32767.0f), 1e-8f);
    for (int i = threadIdx.x * 4; i < DOUT; i += blockDim.x * 4) {
        float4 v = *(const float4*)&p[i];
        v.x = fminf(fmaxf(rintf(__fdiv_rn(v.x, sc)), -32768.0f), 32767.0f) * sc;
        v.y = fminf(fmaxf(rintf(__fdiv_rn(v.y, sc)), -32768.0f), 32767.0f) * sc;
        v.z = fminf(fmaxf(rintf(__fdiv_rn(v.z, sc)), -32768.0f), 32767.0f) * sc;
        v.w = fminf(fmaxf(rintf(__fdiv_rn(v.w, sc)), -32768.0f), 32767.0f) * sc;
        *(float4*)&p[i] = v;
    }
}

// ---------------------------------------------------------------------------
// Launch
// ---------------------------------------------------------------------------
extern "C" void kernel_launch(void* const* d_in, const int* in_sizes, int n_in,
                              void* d_out, int out_size)
{
    const float* d_x = (const float*)d_in[0];
    const float* d_w = (const float*)d_in[1];
    const float* d_b = (const float*)d_in[2];
    const float* d_S = (const float*)d_in[3];
    const float* d_R = (const float*)d_in[4];
    float*       d_o = (float*)d_out;

    float *gW, *gws, *gbias, *gxs, *gbp;
    __half *gA0, *gA1, *gB0, *gB1;
    int8_t *gQ, *gXh, *gXl;
    cudaGetSymbolAddress((void**)&gW,   g_W);
    cudaGetSymbolAddress((void**)&gQ,   g_Q);
    cudaGetSymbolAddress((void**)&gA0,  g_A0);
    cudaGetSymbolAddress((void**)&gA1,  g_A1);
    cudaGetSymbolAddress((void**)&gB0,  g_B0);
    cudaGetSymbolAddress((void**)&gB1,  g_B1);
    cudaGetSymbolAddress((void**)&gXh,  g_Xh);
    cudaGetSymbolAddress((void**)&gXl,  g_Xl);
    cudaGetSymbolAddress((void**)&gxs,  g_xs);
    cudaGetSymbolAddress((void**)&gws,  g_wscale);
    cudaGetSymbolAddress((void**)&gbias, g_bias);
    cudaGetSymbolAddress((void**)&gbp,  g_bpart);

    cudaFuncSetAttribute(gemm1_fused, cudaFuncAttributeMaxDynamicSharedMemorySize, H_SMEM);
    cudaFuncSetAttribute(gemm_s8,     cudaFuncAttributeMaxDynamicSharedMemorySize, S_SMEM);

    // 1) rotated bias (parallel partials + deterministic reduce)
    rot_bias_part<<<dim3(DOUT / 256, 8), 256>>>(d_R, d_b, gbp);
    rot_bias_reduce<<<DOUT / 256, 256>>>(gbp, gbias);

    // 2) prep: fp16 splits for GEMM1; fused per-token x quant for GEMM2
    tsplit2h<<<dim3(DOUT / 32, KR / 32), 256>>>(d_R, KR, DOUT, nullptr, 64.0f, gA0, gA1);
    tsplit2h<<<dim3(DIN / 32, KR / 32),  256>>>(d_w, KR, DIN,  d_S,    64.0f, gB0, gB1);
    xquant_kernel<<<SEQ, 256>>>(d_x, gxs, gXh, gXl);

    // 3) GEMM1 fused: W' = (A0+A1)(B0+B1) keeping 3 significant products,
    //    one K-pass, alpha = 2^-12 un-scale
    {
        dim3 grid(DOUT / 128, DIN / 128);
        gemm1_fused<<<grid, 256, H_SMEM>>>(gA0, gA1, gB0, gB1, KR, gW, DIN, 1.0f / 4096.0f);
    }

    // 4) fused weight rowmax + int8 quantize
    wquant_kernel<<<DOUT, 256>>>(gW, gws, gQ);

    // 5) GEMM2 (int8, exact): out = (x16 @ q^T) * s_tok*s_o + b'
    {
        dim3 grid(SEQ / 128, DOUT / 128);
        gemm_s8<<<grid, 256, S_SMEM>>>(gXh, gXl, gQ, DIN, d_o, DOUT, gxs, gws, gbias);
    }

    // 6) 16-bit per-token fake-quant in place
    out_quant_kernel<<<SEQ, 256>>>(d_o);
}